// round 1
// baseline (speedup 1.0000x reference)
#include <cuda_runtime.h>
#include <math.h>

// ---------------- problem constants ----------------
#define BB 4
#define TT 512
#define DD 768
#define HH 12
#define DKC 64
#define FFC 3072
#define TBN 64
#define NEGV (-1e9f)
#define E_CONST 2.718281828459045f
#define MROWS (BB*TT)            // 2048

// ---------------- scratch layout (floats) ----------------
#define OF_H    0ull                          // LN out       (B*T*D) 1572864
#define OF_Q    1572864ull
#define OF_K    3145728ull
#define OF_V    4718592ull
#define OF_BIAS 6291456ull                    // temporal bias (B*T*T) 1048576
#define OF_S    7340032ull                    // scores (B*H*T*T) 12582912
#define OF_A    19922944ull                   // attn out (B*T*D)
#define OF_X2   21495808ull                   // x + attn proj
#define OF_F    23068672ull                   // ffn hidden (B*T*FF) 6291456
#define SCRATCH_TOTAL 29360128ull             // ~112 MB

__device__ float g_scratch[SCRATCH_TOTAL];

// ---------------- LayerNorm: one block per row ----------------
__global__ __launch_bounds__(256) void ln_kernel(const float* __restrict__ x,
                                                 const float* __restrict__ g,
                                                 const float* __restrict__ b,
                                                 float* __restrict__ out) {
    int row = blockIdx.x;
    const float* xr = x + (size_t)row * DD;
    float s = 0.f, s2 = 0.f;
    for (int i = threadIdx.x; i < DD; i += 256) { float v = xr[i]; s += v; s2 += v * v; }
    #pragma unroll
    for (int o = 16; o > 0; o >>= 1) {
        s  += __shfl_xor_sync(0xffffffffu, s,  o);
        s2 += __shfl_xor_sync(0xffffffffu, s2, o);
    }
    __shared__ float ws[8], ws2[8];
    int w = threadIdx.x >> 5, l = threadIdx.x & 31;
    if (l == 0) { ws[w] = s; ws2[w] = s2; }
    __syncthreads();
    if (w == 0) {
        s  = (l < 8) ? ws[l]  : 0.f;
        s2 = (l < 8) ? ws2[l] : 0.f;
        #pragma unroll
        for (int o = 4; o > 0; o >>= 1) {
            s  += __shfl_xor_sync(0xffffffffu, s,  o);
            s2 += __shfl_xor_sync(0xffffffffu, s2, o);
        }
        if (l == 0) { ws[0] = s; ws2[0] = s2; }
    }
    __syncthreads();
    float mean = ws[0] * (1.f / DD);
    float var  = ws2[0] * (1.f / DD) - mean * mean;
    float inv  = rsqrtf(var + 1e-5f);
    float* orow = out + (size_t)row * DD;
    for (int i = threadIdx.x; i < DD; i += 256)
        orow[i] = (xr[i] - mean) * inv * g[i] + b[i];
}

// ---------------- generic linear GEMM: C = A(M x K) @ W(K x N) + bias [+res / gelu] ----------------
// block tile 64x64, thread tile 4x4, BK=16, 16x16 threads
template <int EPI>  // 0 = bias, 1 = bias + residual, 2 = bias + exact GELU
__global__ __launch_bounds__(256) void gemm_lin(const float* __restrict__ A,
                                                const float* __restrict__ W,
                                                const float* __restrict__ bias,
                                                const float* __restrict__ res,
                                                float* __restrict__ C,
                                                int N, int K) {
    __shared__ float As[16][68];   // padded; rows remain 16B-aligned (68*4=272)
    __shared__ float Bs[16][64];
    int tx = threadIdx.x, ty = threadIdx.y;
    int tid = ty * 16 + tx;
    int m0 = blockIdx.y * 64, n0 = blockIdx.x * 64;
    int kk = tid & 15, r4 = tid >> 4;
    float acc[4][4] = {};

    for (int k0 = 0; k0 < K; k0 += 16) {
        #pragma unroll
        for (int c = 0; c < 4; c++)
            As[kk][r4 * 4 + c] = A[(size_t)(m0 + r4 * 4 + c) * K + k0 + kk];
        #pragma unroll
        for (int it = 0; it < 4; it++) {
            int idx = tid + it * 256;
            Bs[idx >> 6][idx & 63] = W[(size_t)(k0 + (idx >> 6)) * N + n0 + (idx & 63)];
        }
        __syncthreads();
        #pragma unroll
        for (int k = 0; k < 16; k++) {
            float4 a4 = *(const float4*)(&As[k][ty * 4]);
            float4 b4 = *(const float4*)(&Bs[k][tx * 4]);
            float av[4] = {a4.x, a4.y, a4.z, a4.w};
            float bv[4] = {b4.x, b4.y, b4.z, b4.w};
            #pragma unroll
            for (int i = 0; i < 4; i++)
                #pragma unroll
                for (int j = 0; j < 4; j++)
                    acc[i][j] = fmaf(av[i], bv[j], acc[i][j]);
        }
        __syncthreads();
    }

    #pragma unroll
    for (int i = 0; i < 4; i++) {
        int m = m0 + ty * 4 + i;
        #pragma unroll
        for (int j = 0; j < 4; j++) {
            int n = n0 + tx * 4 + j;
            float v = acc[i][j] + bias[n];
            if (EPI == 1) v += res[(size_t)m * N + n];
            if (EPI == 2) v = 0.5f * v * (1.f + erff(v * 0.70710678118654752f));
            C[(size_t)m * N + n] = v;
        }
    }
}

// ---------------- temporal bias: bias(b,i,j) = MLP(1/log(e+tm)), head-independent ----------------
__global__ __launch_bounds__(256) void bias_kernel(const float* __restrict__ tm,
                                                   const float* __restrict__ t1w,
                                                   const float* __restrict__ t1b,
                                                   const float* __restrict__ t2w,
                                                   const float* __restrict__ t2b) {
    __shared__ float w1[TBN], b1[TBN], w2[TBN];
    int t = threadIdx.x;
    if (t < TBN) { w1[t] = t1w[t]; b1[t] = t1b[t]; w2[t] = t2w[t]; }
    __syncthreads();
    size_t idx = (size_t)blockIdx.x * 256 + t;          // < B*T*T
    float u = 1.f / logf(E_CONST + tm[idx]);
    float s = t2b[0];
    #pragma unroll
    for (int k = 0; k < TBN; k++) {
        float z = fmaf(u, w1[k], b1[k]);
        z = (z > 0.f) ? z : 0.2f * z;
        s = fmaf(z, w2[k], s);
    }
    g_scratch[OF_BIAS + idx] = s;
}

// ---------------- QK^T + scale + bias + masks -> scores ----------------
// grid (T/64, T/64, B*H), block 16x16
__global__ __launch_bounds__(256) void qk_kernel(const int* __restrict__ pm) {
    __shared__ float Qs[64][68];  // [d][i]
    __shared__ float Ks[64][68];  // [d][j]
    int tx = threadIdx.x, ty = threadIdx.y;
    int tid = ty * 16 + tx;
    int z = blockIdx.z, b = z / HH, h = z % HH;
    int i0 = blockIdx.y * 64, j0 = blockIdx.x * 64;

    const float* gq = g_scratch + OF_Q;
    const float* gk = g_scratch + OF_K;
    #pragma unroll
    for (int it = 0; it < 16; it++) {
        int idx = tid + it * 256;
        int il = idx >> 6, d = idx & 63;
        Qs[d][il] = gq[(size_t)(b * TT + i0 + il) * DD + h * DKC + d];
        Ks[d][il] = gk[(size_t)(b * TT + j0 + il) * DD + h * DKC + d];
    }
    __syncthreads();

    float acc[4][4] = {};
    #pragma unroll 8
    for (int k = 0; k < 64; k++) {
        float4 a4 = *(const float4*)(&Qs[k][ty * 4]);
        float4 b4 = *(const float4*)(&Ks[k][tx * 4]);
        float av[4] = {a4.x, a4.y, a4.z, a4.w};
        float bv[4] = {b4.x, b4.y, b4.z, b4.w};
        #pragma unroll
        for (int i = 0; i < 4; i++)
            #pragma unroll
            for (int j = 0; j < 4; j++)
                acc[i][j] = fmaf(av[i], bv[j], acc[i][j]);
    }

    const int*   pmB   = pm + (size_t)b * TT * TT;
    const float* biasB = g_scratch + OF_BIAS + (size_t)b * TT * TT;
    float*       scB   = g_scratch + OF_S + (size_t)z * TT * TT;
    #pragma unroll
    for (int i = 0; i < 4; i++) {
        int gi = i0 + ty * 4 + i;
        #pragma unroll
        for (int j = 0; j < 4; j++) {
            int gj = j0 + tx * 4 + j;
            size_t off = (size_t)gi * TT + gj;
            bool masked = (pmB[off] == 0) || (gj > gi && gi > 0);
            scB[off] = masked ? NEGV : fmaf(acc[i][j], 0.125f, biasB[off]);
        }
    }
}

// ---------------- softmax over last dim (row length 512), one block per row ----------------
__global__ __launch_bounds__(256) void softmax_kernel() {
    float* r = g_scratch + OF_S + (size_t)blockIdx.x * TT;
    int t = threadIdx.x;
    float v0 = r[t], v1 = r[t + 256];
    float m = fmaxf(v0, v1);
    #pragma unroll
    for (int o = 16; o > 0; o >>= 1) m = fmaxf(m, __shfl_xor_sync(0xffffffffu, m, o));
    __shared__ float sm[8];
    int w = t >> 5, l = t & 31;
    if (l == 0) sm[w] = m;
    __syncthreads();
    if (w == 0) {
        m = (l < 8) ? sm[l] : -INFINITY;
        #pragma unroll
        for (int o = 4; o > 0; o >>= 1) m = fmaxf(m, __shfl_xor_sync(0xffffffffu, m, o));
        if (l == 0) sm[0] = m;
    }
    __syncthreads();
    m = sm[0];
    float e0 = expf(v0 - m), e1 = expf(v1 - m);
    float s = e0 + e1;
    #pragma unroll
    for (int o = 16; o > 0; o >>= 1) s += __shfl_xor_sync(0xffffffffu, s, o);
    __shared__ float ss[8];
    if (l == 0) ss[w] = s;
    __syncthreads();
    if (w == 0) {
        s = (l < 8) ? ss[l] : 0.f;
        #pragma unroll
        for (int o = 4; o > 0; o >>= 1) s += __shfl_xor_sync(0xffffffffu, s, o);
        if (l == 0) ss[0] = s;
    }
    __syncthreads();
    float inv = 1.f / ss[0];
    r[t] = e0 * inv;
    r[t + 256] = e1 * inv;
}

// ---------------- P @ V -> attn out (B,T,H,DK) ----------------
// grid (T/64, B*H), block 16x16. M=512,N=64,K=512 per (b,h)
__global__ __launch_bounds__(256) void pv_kernel() {
    __shared__ float As[16][68];
    __shared__ float Bs[16][64];
    int tx = threadIdx.x, ty = threadIdx.y;
    int tid = ty * 16 + tx;
    int z = blockIdx.y, b = z / HH, h = z % HH;
    int i0 = blockIdx.x * 64;
    int kk = tid & 15, r4 = tid >> 4;

    const float* P  = g_scratch + OF_S + (size_t)z * TT * TT;
    const float* gv = g_scratch + OF_V;
    float acc[4][4] = {};

    for (int k0 = 0; k0 < TT; k0 += 16) {
        #pragma unroll
        for (int c = 0; c < 4; c++)
            As[kk][r4 * 4 + c] = P[(size_t)(i0 + r4 * 4 + c) * TT + k0 + kk];
        #pragma unroll
        for (int it = 0; it < 4; it++) {
            int idx = tid + it * 256;
            Bs[idx >> 6][idx & 63] = gv[(size_t)(b * TT + k0 + (idx >> 6)) * DD + h * DKC + (idx & 63)];
        }
        __syncthreads();
        #pragma unroll
        for (int k = 0; k < 16; k++) {
            float4 a4 = *(const float4*)(&As[k][ty * 4]);
            float4 b4 = *(const float4*)(&Bs[k][tx * 4]);
            float av[4] = {a4.x, a4.y, a4.z, a4.w};
            float bv[4] = {b4.x, b4.y, b4.z, b4.w};
            #pragma unroll
            for (int i = 0; i < 4; i++)
                #pragma unroll
                for (int j = 0; j < 4; j++)
                    acc[i][j] = fmaf(av[i], bv[j], acc[i][j]);
        }
        __syncthreads();
    }

    float* ao = g_scratch + OF_A;
    #pragma unroll
    for (int i = 0; i < 4; i++) {
        int gi = i0 + ty * 4 + i;
        #pragma unroll
        for (int j = 0; j < 4; j++)
            ao[(size_t)(b * TT + gi) * DD + h * DKC + tx * 4 + j] = acc[i][j];
    }
}

// ---------------- launch ----------------
extern "C" void kernel_launch(void* const* d_in, const int* in_sizes, int n_in,
                              void* d_out, int out_size) {
    const float* x     = (const float*)d_in[0];
    const float* tmat  = (const float*)d_in[1];
    const int*   pm    = (const int*)d_in[2];
    const float* wq = (const float*)d_in[3],  *bq = (const float*)d_in[4];
    const float* wk = (const float*)d_in[5],  *bk = (const float*)d_in[6];
    const float* wv = (const float*)d_in[7],  *bv = (const float*)d_in[8];
    const float* wp = (const float*)d_in[9],  *bp = (const float*)d_in[10];
    const float* t1w = (const float*)d_in[11], *t1b = (const float*)d_in[12];
    const float* t2w = (const float*)d_in[13], *t2b = (const float*)d_in[14];
    const float* f1w = (const float*)d_in[15], *f1b = (const float*)d_in[16];
    const float* f2w = (const float*)d_in[17], *f2b = (const float*)d_in[18];
    const float* ln1g = (const float*)d_in[19], *ln1b = (const float*)d_in[20];
    const float* ln2g = (const float*)d_in[21], *ln2b = (const float*)d_in[22];
    float* out = (float*)d_out;

    float* sc = nullptr;
    cudaGetSymbolAddress((void**)&sc, g_scratch);
    float* gH  = sc + OF_H;
    float* gQ  = sc + OF_Q;
    float* gK  = sc + OF_K;
    float* gV  = sc + OF_V;
    float* gA  = sc + OF_A;
    float* gX2 = sc + OF_X2;
    float* gF  = sc + OF_F;

    dim3 blk(16, 16);

    // pre-LN attention
    ln_kernel<<<MROWS, 256>>>(x, ln1g, ln1b, gH);
    gemm_lin<0><<<dim3(DD / 64, MROWS / 64), blk>>>(gH, wq, bq, nullptr, gQ, DD, DD);
    gemm_lin<0><<<dim3(DD / 64, MROWS / 64), blk>>>(gH, wk, bk, nullptr, gK, DD, DD);
    gemm_lin<0><<<dim3(DD / 64, MROWS / 64), blk>>>(gH, wv, bv, nullptr, gV, DD, DD);

    bias_kernel<<<(BB * TT * TT) / 256, 256>>>(tmat, t1w, t1b, t2w, t2b);
    qk_kernel<<<dim3(TT / 64, TT / 64, BB * HH), blk>>>(pm);
    softmax_kernel<<<BB * HH * TT, 256>>>();
    pv_kernel<<<dim3(TT / 64, BB * HH), blk>>>();

    // out proj + residual
    gemm_lin<1><<<dim3(DD / 64, MROWS / 64), blk>>>(gA, wp, bp, x, gX2, DD, DD);

    // pre-LN FFN
    ln_kernel<<<MROWS, 256>>>(gX2, ln2g, ln2b, gH);
    gemm_lin<2><<<dim3(FFC / 64, MROWS / 64), blk>>>(gH, f1w, f1b, nullptr, gF, FFC, DD);
    gemm_lin<1><<<dim3(DD / 64, MROWS / 64), blk>>>(gF, f2w, f2b, gX2, out, DD, FFC);
}

// round 3
// speedup vs baseline: 1.7857x; 1.7857x over previous
#include <cuda_runtime.h>
#include <math.h>
#include <stdint.h>

// ---------------- problem constants ----------------
#define BB 4
#define TT 512
#define DD 768
#define HH 12
#define DKC 64
#define FFC 3072
#define TBN 64
#define NEGV (-1e9f)
#define E_CONST 2.718281828459045f
#define MROWS (BB*TT)            // 2048

// ---------------- scratch layout (floats) ----------------
#define OF_H    0ull
#define OF_Q    1572864ull
#define OF_K    3145728ull
#define OF_V    4718592ull
#define OF_BIAS 6291456ull
#define OF_S    7340032ull
#define OF_A    19922944ull
#define OF_X2   21495808ull
#define OF_F    23068672ull
#define OF_WQT  29360128ull
#define OF_WKT  29949952ull
#define OF_WVT  30539776ull
#define OF_WPT  31129600ull
#define OF_F1T  31719424ull
#define OF_F2T  34078720ull
#define SCRATCH_TOTAL 36438016ull

__device__ float g_scratch[SCRATCH_TOTAL];

// ---------------- helpers ----------------
__device__ __forceinline__ uint32_t smem_u32(const void* p) {
    uint32_t a;
    asm("{ .reg .u64 t; cvta.to.shared.u64 t, %1; cvt.u32.u64 %0, t; }" : "=r"(a) : "l"(p));
    return a;
}
__device__ __forceinline__ float f2tf32f(float f) {
    uint32_t r; asm("cvt.rna.tf32.f32 %0, %1;" : "=r"(r) : "f"(f));
    return __uint_as_float(r);
}
#define CP_ASYNC16(dst_u32, src_ptr) \
    asm volatile("cp.async.cg.shared.global [%0], [%1], 16;\n" :: "r"(dst_u32), "l"(__cvta_generic_to_global(src_ptr)))
#define CP_COMMIT() asm volatile("cp.async.commit_group;\n" ::: "memory")
#define CP_WAIT1()  asm volatile("cp.async.wait_group 1;\n" ::: "memory")

#define MMA_TF32(c0,c1,c2,c3,a0,a1,a2,a3,b0,b1) \
    asm volatile("mma.sync.aligned.m16n8k8.row.col.f32.tf32.tf32.f32 " \
                 "{%0,%1,%2,%3}, {%4,%5,%6,%7}, {%8,%9}, {%0,%1,%2,%3};\n" \
                 : "+f"(c0), "+f"(c1), "+f"(c2), "+f"(c3) \
                 : "r"(a0), "r"(a1), "r"(a2), "r"(a3), "r"(b0), "r"(b1))

// =======================================================================
// tf32 mma.sync GEMM: C[M,N] = A[M,K] @ Wt[N,K]^T (+bias / +res / gelu)
// block tile 128x64, warp grid 4(m) x 2(n) -> warp tile 32x32
// BK=16, cp.async double buffer, smem row stride 20 floats (conflict-free)
// A and Wt must be pre-rounded to tf32-representable values.
// =======================================================================
#define BM 128
#define BN 64
#define LDT 20

template <int EPI>  // 0 bias, 1 bias+res, 2 bias+gelu(+tf32 round)
__global__ __launch_bounds__(256, 2) void gemm_mma(const float* __restrict__ A,
                                                   const float* __restrict__ Wt,
                                                   const float* __restrict__ bias,
                                                   const float* __restrict__ res,
                                                   float* __restrict__ C,
                                                   int N, int K) {
    __shared__ float As[2][BM * LDT];
    __shared__ float Bs[2][BN * LDT];

    int tid = threadIdx.x;
    int warp = tid >> 5, lane = tid & 31;
    int wm = warp >> 1, wn = warp & 1;           // 4 x 2
    int g = lane >> 2, tig = lane & 3;
    int m0 = blockIdx.y * BM, n0 = blockIdx.x * BN;

    // global->smem chunk mapping (16B chunks)
    int ar0 = tid >> 2,            ac0 = (tid & 3) * 4;          // A chunk 1 (rows 0..63)
    int ar1 = (tid + 256) >> 2,    ac1 = ((tid + 256) & 3) * 4;  // A chunk 2 (rows 64..127)
    int br  = tid >> 2,            bc  = (tid & 3) * 4;          // B chunk (rows 0..63)

    uint32_t sA = smem_u32(&As[0][0]);
    uint32_t sB = smem_u32(&Bs[0][0]);
    const uint32_t bufA = BM * LDT * 4, bufB = BN * LDT * 4;

    const int nk = K >> 4;

    // prefetch tiles 0 and 1
    #pragma unroll
    for (int pf = 0; pf < 2; pf++) {
        int k0 = pf * 16;
        CP_ASYNC16(sA + pf * bufA + (ar0 * LDT + ac0) * 4, A + (size_t)(m0 + ar0) * K + k0 + ac0);
        CP_ASYNC16(sA + pf * bufA + (ar1 * LDT + ac1) * 4, A + (size_t)(m0 + ar1) * K + k0 + ac1);
        CP_ASYNC16(sB + pf * bufB + (br * LDT + bc) * 4,  Wt + (size_t)(n0 + br) * K + k0 + bc);
        CP_COMMIT();
    }

    float c[2][4][4];
    #pragma unroll
    for (int i = 0; i < 2; i++)
        #pragma unroll
        for (int j = 0; j < 4; j++)
            #pragma unroll
            for (int e = 0; e < 4; e++) c[i][j][e] = 0.f;

    for (int kt = 0; kt < nk; kt++) {
        int buf = kt & 1;
        CP_WAIT1();
        __syncthreads();

        const float* as = As[buf];
        const float* bs = Bs[buf];
        #pragma unroll
        for (int ks = 0; ks < 2; ks++) {
            int kb = ks * 8;
            uint32_t a[2][4], b[4][2];
            #pragma unroll
            for (int i = 0; i < 2; i++) {
                int r = wm * 32 + i * 16;
                a[i][0] = __float_as_uint(as[(r + g)     * LDT + kb + tig]);
                a[i][1] = __float_as_uint(as[(r + 8 + g) * LDT + kb + tig]);
                a[i][2] = __float_as_uint(as[(r + g)     * LDT + kb + tig + 4]);
                a[i][3] = __float_as_uint(as[(r + 8 + g) * LDT + kb + tig + 4]);
            }
            #pragma unroll
            for (int j = 0; j < 4; j++) {
                int r = wn * 32 + j * 8 + g;
                b[j][0] = __float_as_uint(bs[r * LDT + kb + tig]);
                b[j][1] = __float_as_uint(bs[r * LDT + kb + tig + 4]);
            }
            #pragma unroll
            for (int i = 0; i < 2; i++)
                #pragma unroll
                for (int j = 0; j < 4; j++)
                    MMA_TF32(c[i][j][0], c[i][j][1], c[i][j][2], c[i][j][3],
                             a[i][0], a[i][1], a[i][2], a[i][3], b[j][0], b[j][1]);
        }
        __syncthreads();
        if (kt + 2 < nk) {
            int k0 = (kt + 2) * 16;
            CP_ASYNC16(sA + buf * bufA + (ar0 * LDT + ac0) * 4, A + (size_t)(m0 + ar0) * K + k0 + ac0);
            CP_ASYNC16(sA + buf * bufA + (ar1 * LDT + ac1) * 4, A + (size_t)(m0 + ar1) * K + k0 + ac1);
            CP_ASYNC16(sB + buf * bufB + (br * LDT + bc) * 4,  Wt + (size_t)(n0 + br) * K + k0 + bc);
        }
        CP_COMMIT();   // keep group count in lockstep even when empty
    }

    // epilogue
    #pragma unroll
    for (int i = 0; i < 2; i++) {
        int row0 = m0 + wm * 32 + i * 16 + g;
        #pragma unroll
        for (int j = 0; j < 4; j++) {
            int col = n0 + wn * 32 + j * 8 + 2 * tig;
            float b0 = bias[col], b1 = bias[col + 1];
            #pragma unroll
            for (int half = 0; half < 2; half++) {
                int r = row0 + half * 8;
                float v0 = c[i][j][half * 2 + 0] + b0;
                float v1 = c[i][j][half * 2 + 1] + b1;
                if (EPI == 1) {
                    float2 r2 = *(const float2*)(res + (size_t)r * N + col);
                    v0 += r2.x; v1 += r2.y;
                }
                if (EPI == 2) {
                    v0 = 0.5f * v0 * (1.f + erff(v0 * 0.70710678118654752f));
                    v1 = 0.5f * v1 * (1.f + erff(v1 * 0.70710678118654752f));
                    v0 = f2tf32f(v0); v1 = f2tf32f(v1);   // feeds FFN2 GEMM
                }
                float2 o; o.x = v0; o.y = v1;
                *(float2*)(C + (size_t)r * N + col) = o;
            }
        }
    }
}

// ---------------- weight transpose: W[K][N] -> Wt[N][K] (tf32-rounded) ----------------
__global__ __launch_bounds__(256) void transpose_kernel(const float* __restrict__ W,
                                                        float* __restrict__ Wt,
                                                        int K, int N) {
    __shared__ float t[32][33];
    int n0 = blockIdx.x * 32, k0 = blockIdx.y * 32;
    int tx = threadIdx.x, ty = threadIdx.y;
    #pragma unroll
    for (int i = 0; i < 32; i += 8)
        t[ty + i][tx] = W[(size_t)(k0 + ty + i) * N + n0 + tx];
    __syncthreads();
    #pragma unroll
    for (int i = 0; i < 32; i += 8)
        Wt[(size_t)(n0 + ty + i) * K + k0 + tx] = f2tf32f(t[tx][ty + i]);
}

// ---------------- LayerNorm (tf32-rounded output; feeds GEMMs) ----------------
__global__ __launch_bounds__(256) void ln_kernel(const float* __restrict__ x,
                                                 const float* __restrict__ g,
                                                 const float* __restrict__ b,
                                                 float* __restrict__ out) {
    int row = blockIdx.x;
    const float* xr = x + (size_t)row * DD;
    float s = 0.f, s2 = 0.f;
    for (int i = threadIdx.x; i < DD; i += 256) { float v = xr[i]; s += v; s2 += v * v; }
    #pragma unroll
    for (int o = 16; o > 0; o >>= 1) {
        s  += __shfl_xor_sync(0xffffffffu, s,  o);
        s2 += __shfl_xor_sync(0xffffffffu, s2, o);
    }
    __shared__ float ws[8], ws2[8];
    int w = threadIdx.x >> 5, l = threadIdx.x & 31;
    if (l == 0) { ws[w] = s; ws2[w] = s2; }
    __syncthreads();
    if (w == 0) {
        s  = (l < 8) ? ws[l]  : 0.f;
        s2 = (l < 8) ? ws2[l] : 0.f;
        #pragma unroll
        for (int o = 4; o > 0; o >>= 1) {
            s  += __shfl_xor_sync(0xffffffffu, s,  o);
            s2 += __shfl_xor_sync(0xffffffffu, s2, o);
        }
        if (l == 0) { ws[0] = s; ws2[0] = s2; }
    }
    __syncthreads();
    float mean = ws[0] * (1.f / DD);
    float var  = ws2[0] * (1.f / DD) - mean * mean;
    float inv  = rsqrtf(var + 1e-5f);
    float* orow = out + (size_t)row * DD;
    for (int i = threadIdx.x; i < DD; i += 256)
        orow[i] = f2tf32f((xr[i] - mean) * inv * g[i] + b[i]);
}

// ---------------- temporal bias ----------------
__global__ __launch_bounds__(256) void bias_kernel(const float* __restrict__ tm,
                                                   const float* __restrict__ t1w,
                                                   const float* __restrict__ t1b,
                                                   const float* __restrict__ t2w,
                                                   const float* __restrict__ t2b) {
    __shared__ float w1[TBN], b1[TBN], w2[TBN];
    int t = threadIdx.x;
    if (t < TBN) { w1[t] = t1w[t]; b1[t] = t1b[t]; w2[t] = t2w[t]; }
    __syncthreads();
    size_t idx = (size_t)blockIdx.x * 256 + t;
    float u = 1.f / logf(E_CONST + tm[idx]);
    float s = t2b[0];
    #pragma unroll
    for (int k = 0; k < TBN; k++) {
        float z = fmaf(u, w1[k], b1[k]);
        z = (z > 0.f) ? z : 0.2f * z;
        s = fmaf(z, w2[k], s);
    }
    g_scratch[OF_BIAS + idx] = s;
}

// ---------------- QK^T + scale + bias + masks ----------------
__global__ __launch_bounds__(256) void qk_kernel(const int* __restrict__ pm) {
    __shared__ float Qs[64][68];
    __shared__ float Ks[64][68];
    int tx = threadIdx.x, ty = threadIdx.y;
    int tid = ty * 16 + tx;
    int z = blockIdx.z, b = z / HH, h = z % HH;
    int i0 = blockIdx.y * 64, j0 = blockIdx.x * 64;

    const float* gq = g_scratch + OF_Q;
    const float* gk = g_scratch + OF_K;
    #pragma unroll
    for (int it = 0; it < 16; it++) {
        int idx = tid + it * 256;
        int il = idx >> 6, d = idx & 63;
        Qs[d][il] = gq[(size_t)(b * TT + i0 + il) * DD + h * DKC + d];
        Ks[d][il] = gk[(size_t)(b * TT + j0 + il) * DD + h * DKC + d];
    }
    __syncthreads();

    float acc[4][4] = {};
    #pragma unroll 8
    for (int k = 0; k < 64; k++) {
        float4 a4 = *(const float4*)(&Qs[k][ty * 4]);
        float4 b4 = *(const float4*)(&Ks[k][tx * 4]);
        float av[4] = {a4.x, a4.y, a4.z, a4.w};
        float bv[4] = {b4.x, b4.y, b4.z, b4.w};
        #pragma unroll
        for (int i = 0; i < 4; i++)
            #pragma unroll
            for (int j = 0; j < 4; j++)
                acc[i][j] = fmaf(av[i], bv[j], acc[i][j]);
    }

    const int*   pmB   = pm + (size_t)b * TT * TT;
    const float* biasB = g_scratch + OF_BIAS + (size_t)b * TT * TT;
    float*       scB   = g_scratch + OF_S + (size_t)z * TT * TT;
    #pragma unroll
    for (int i = 0; i < 4; i++) {
        int gi = i0 + ty * 4 + i;
        #pragma unroll
        for (int j = 0; j < 4; j++) {
            int gj = j0 + tx * 4 + j;
            size_t off = (size_t)gi * TT + gj;
            bool masked = (pmB[off] == 0) || (gj > gi && gi > 0);
            scB[off] = masked ? NEGV : fmaf(acc[i][j], 0.125f, biasB[off]);
        }
    }
}

// ---------------- softmax ----------------
__global__ __launch_bounds__(256) void softmax_kernel() {
    float* r = g_scratch + OF_S + (size_t)blockIdx.x * TT;
    int t = threadIdx.x;
    float v0 = r[t], v1 = r[t + 256];
    float m = fmaxf(v0, v1);
    #pragma unroll
    for (int o = 16; o > 0; o >>= 1) m = fmaxf(m, __shfl_xor_sync(0xffffffffu, m, o));
    __shared__ float sm[8];
    int w = t >> 5, l = t & 31;
    if (l == 0) sm[w] = m;
    __syncthreads();
    if (w == 0) {
        m = (l < 8) ? sm[l] : -INFINITY;
        #pragma unroll
        for (int o = 4; o > 0; o >>= 1) m = fmaxf(m, __shfl_xor_sync(0xffffffffu, m, o));
        if (l == 0) sm[0] = m;
    }
    __syncthreads();
    m = sm[0];
    float e0 = expf(v0 - m), e1 = expf(v1 - m);
    float s = e0 + e1;
    #pragma unroll
    for (int o = 16; o > 0; o >>= 1) s += __shfl_xor_sync(0xffffffffu, s, o);
    __shared__ float ss[8];
    if (l == 0) ss[w] = s;
    __syncthreads();
    if (w == 0) {
        s = (l < 8) ? ss[l] : 0.f;
        #pragma unroll
        for (int o = 4; o > 0; o >>= 1) s += __shfl_xor_sync(0xffffffffu, s, o);
        if (l == 0) ss[0] = s;
    }
    __syncthreads();
    float inv = 1.f / ss[0];
    r[t] = e0 * inv;
    r[t + 256] = e1 * inv;
}

// ---------------- P @ V (tf32-rounded output; feeds out-proj GEMM) ----------------
__global__ __launch_bounds__(256) void pv_kernel() {
    __shared__ float As[16][68];
    __shared__ float Bs[16][64];
    int tx = threadIdx.x, ty = threadIdx.y;
    int tid = ty * 16 + tx;
    int z = blockIdx.y, b = z / HH, h = z % HH;
    int i0 = blockIdx.x * 64;
    int kk = tid & 15, r4 = tid >> 4;

    const float* P  = g_scratch + OF_S + (size_t)z * TT * TT;
    const float* gv = g_scratch + OF_V;
    float acc[4][4] = {};

    for (int k0 = 0; k0 < TT; k0 += 16) {
        #pragma unroll
        for (int c = 0; c < 4; c++)
            As[kk][r4 * 4 + c] = P[(size_t)(i0 + r4 * 4 + c) * TT + k0 + kk];
        #pragma unroll
        for (int it = 0; it < 4; it++) {
            int idx = tid + it * 256;
            Bs[idx >> 6][idx & 63] = gv[(size_t)(b * TT + k0 + (idx >> 6)) * DD + h * DKC + (idx & 63)];
        }
        __syncthreads();
        #pragma unroll
        for (int k = 0; k < 16; k++) {
            float4 a4 = *(const float4*)(&As[k][ty * 4]);
            float4 b4 = *(const float4*)(&Bs[k][tx * 4]);
            float av[4] = {a4.x, a4.y, a4.z, a4.w};
            float bv[4] = {b4.x, b4.y, b4.z, b4.w};
            #pragma unroll
            for (int i = 0; i < 4; i++)
                #pragma unroll
                for (int j = 0; j < 4; j++)
                    acc[i][j] = fmaf(av[i], bv[j], acc[i][j]);
        }
        __syncthreads();
    }

    float* ao = g_scratch + OF_A;
    #pragma unroll
    for (int i = 0; i < 4; i++) {
        int gi = i0 + ty * 4 + i;
        #pragma unroll
        for (int j = 0; j < 4; j++)
            ao[(size_t)(b * TT + gi) * DD + h * DKC + tx * 4 + j] = f2tf32f(acc[i][j]);
    }
}

// ---------------- launch ----------------
extern "C" void kernel_launch(void* const* d_in, const int* in_sizes, int n_in,
                              void* d_out, int out_size) {
    const float* x     = (const float*)d_in[0];
    const float* tmat  = (const float*)d_in[1];
    const int*   pm    = (const int*)d_in[2];
    const float* wq = (const float*)d_in[3],  *bq = (const float*)d_in[4];
    const float* wk = (const float*)d_in[5],  *bk = (const float*)d_in[6];
    const float* wv = (const float*)d_in[7],  *bv = (const float*)d_in[8];
    const float* wp = (const float*)d_in[9],  *bp = (const float*)d_in[10];
    const float* t1w = (const float*)d_in[11], *t1b = (const float*)d_in[12];
    const float* t2w = (const float*)d_in[13], *t2b = (const float*)d_in[14];
    const float* f1w = (const float*)d_in[15], *f1b = (const float*)d_in[16];
    const float* f2w = (const float*)d_in[17], *f2b = (const float*)d_in[18];
    const float* ln1g = (const float*)d_in[19], *ln1b = (const float*)d_in[20];
    const float* ln2g = (const float*)d_in[21], *ln2b = (const float*)d_in[22];
    float* out = (float*)d_out;

    float* sc = nullptr;
    cudaGetSymbolAddress((void**)&sc, g_scratch);
    float* gH   = sc + OF_H;
    float* gQ   = sc + OF_Q;
    float* gK   = sc + OF_K;
    float* gV   = sc + OF_V;
    float* gA   = sc + OF_A;
    float* gX2  = sc + OF_X2;
    float* gF   = sc + OF_F;
    float* wqT  = sc + OF_WQT;
    float* wkT  = sc + OF_WKT;
    float* wvT  = sc + OF_WVT;
    float* wpT  = sc + OF_WPT;
    float* f1T  = sc + OF_F1T;
    float* f2T  = sc + OF_F2T;

    dim3 tb(32, 8);
    transpose_kernel<<<dim3(DD / 32, DD / 32), tb>>>(wq, wqT, DD, DD);
    transpose_kernel<<<dim3(DD / 32, DD / 32), tb>>>(wk, wkT, DD, DD);
    transpose_kernel<<<dim3(DD / 32, DD / 32), tb>>>(wv, wvT, DD, DD);
    transpose_kernel<<<dim3(DD / 32, DD / 32), tb>>>(wp, wpT, DD, DD);
    transpose_kernel<<<dim3(FFC / 32, DD / 32), tb>>>(f1w, f1T, DD, FFC);
    transpose_kernel<<<dim3(DD / 32, FFC / 32), tb>>>(f2w, f2T, FFC, DD);

    // pre-LN attention
    ln_kernel<<<MROWS, 256>>>(x, ln1g, ln1b, gH);
    gemm_mma<0><<<dim3(DD / BN, MROWS / BM), 256>>>(gH, wqT, bq, nullptr, gQ, DD, DD);
    gemm_mma<0><<<dim3(DD / BN, MROWS / BM), 256>>>(gH, wkT, bk, nullptr, gK, DD, DD);
    gemm_mma<0><<<dim3(DD / BN, MROWS / BM), 256>>>(gH, wvT, bv, nullptr, gV, DD, DD);

    bias_kernel<<<(BB * TT * TT) / 256, 256>>>(tmat, t1w, t1b, t2w, t2b);
    qk_kernel<<<dim3(TT / 64, TT / 64, BB * HH), dim3(16, 16)>>>(pm);
    softmax_kernel<<<BB * HH * TT, 256>>>();
    pv_kernel<<<dim3(TT / 64, BB * HH), dim3(16, 16)>>>();

    // out proj + residual
    gemm_mma<1><<<dim3(DD / BN, MROWS / BM), 256>>>(gA, wpT, bp, x, gX2, DD, DD);

    // pre-LN FFN
    ln_kernel<<<MROWS, 256>>>(gX2, ln2g, ln2b, gH);
    gemm_mma<2><<<dim3(FFC / BN, MROWS / BM), 256>>>(gH, f1T, f1b, nullptr, gF, FFC, DD);
    gemm_mma<1><<<dim3(DD / BN, MROWS / BM), 256>>>(gF, f2T, f2b, gX2, out, DD, FFC);
}

// round 5
// speedup vs baseline: 2.3584x; 1.3207x over previous
#include <cuda_runtime.h>
#include <math.h>
#include <stdint.h>

// ---------------- problem constants ----------------
#define BB 4
#define TT 512
#define DD 768
#define HH 12
#define DKC 64
#define FFC 3072
#define TBN 64
#define NEGV (-1e9f)
#define E_CONST 2.718281828459045f
#define MROWS (BB*TT)            // 2048

// ---------------- scratch layout (floats) ----------------
#define OF_H    0ull
#define OF_BIAS 6291456ull                    // biasM with masks baked in (B*T*T)
#define OF_S    7340032ull                    // reused: QKV output (2048 x 2304) + concat bias
#define OF_QKV  OF_S
#define OF_BQKV (OF_S + 4718592ull)           // 2304 floats
#define OF_A    19922944ull
#define OF_X2   21495808ull
#define OF_F    23068672ull
#define OF_WQT  29360128ull                   // combined WqkvT [2304][768]
#define OF_WPT  31129600ull
#define OF_F1T  31719424ull
#define OF_F2T  34078720ull
#define SCRATCH_TOTAL 36438016ull

__device__ float g_scratch[SCRATCH_TOTAL];

// ---------------- helpers ----------------
__device__ __forceinline__ uint32_t smem_u32(const void* p) {
    uint32_t a;
    asm("{ .reg .u64 t; cvta.to.shared.u64 t, %1; cvt.u32.u64 %0, t; }" : "=r"(a) : "l"(p));
    return a;
}
__device__ __forceinline__ float f2tf32f(float f) {
    uint32_t r; asm("cvt.rna.tf32.f32 %0, %1;" : "=r"(r) : "f"(f));
    return __uint_as_float(r);
}
#define CP_ASYNC16(dst_u32, src_ptr) \
    asm volatile("cp.async.cg.shared.global [%0], [%1], 16;\n" :: "r"(dst_u32), "l"(__cvta_generic_to_global(src_ptr)))
#define CP_COMMIT() asm volatile("cp.async.commit_group;\n" ::: "memory")
#define CP_WAIT1()  asm volatile("cp.async.wait_group 1;\n" ::: "memory")
#define CP_WAIT0()  asm volatile("cp.async.wait_group 0;\n" ::: "memory")

#define MMA_TF32(c0,c1,c2,c3,a0,a1,a2,a3,b0,b1) \
    asm volatile("mma.sync.aligned.m16n8k8.row.col.f32.tf32.tf32.f32 " \
                 "{%0,%1,%2,%3}, {%4,%5,%6,%7}, {%8,%9}, {%0,%1,%2,%3};\n" \
                 : "+f"(c0), "+f"(c1), "+f"(c2), "+f"(c3) \
                 : "r"(a0), "r"(a1), "r"(a2), "r"(a3), "r"(b0), "r"(b1))

// =======================================================================
// tf32 mma.sync GEMM  (unchanged — validated in R3)
// =======================================================================
#define BM 128
#define BN 64
#define LDT 20

template <int EPI>  // 0 bias, 1 bias+res, 2 bias+gelu(+tf32 round)
__global__ __launch_bounds__(256, 2) void gemm_mma(const float* __restrict__ A,
                                                   const float* __restrict__ Wt,
                                                   const float* __restrict__ bias,
                                                   const float* __restrict__ res,
                                                   float* __restrict__ C,
                                                   int N, int K) {
    __shared__ float As[2][BM * LDT];
    __shared__ float Bs[2][BN * LDT];

    int tid = threadIdx.x;
    int warp = tid >> 5, lane = tid & 31;
    int wm = warp >> 1, wn = warp & 1;
    int g = lane >> 2, tig = lane & 3;
    int m0 = blockIdx.y * BM, n0 = blockIdx.x * BN;

    int ar0 = tid >> 2,            ac0 = (tid & 3) * 4;
    int ar1 = (tid + 256) >> 2,    ac1 = ((tid + 256) & 3) * 4;
    int br  = tid >> 2,            bc  = (tid & 3) * 4;

    uint32_t sA = smem_u32(&As[0][0]);
    uint32_t sB = smem_u32(&Bs[0][0]);
    const uint32_t bufA = BM * LDT * 4, bufB = BN * LDT * 4;

    const int nk = K >> 4;

    #pragma unroll
    for (int pf = 0; pf < 2; pf++) {
        int k0 = pf * 16;
        CP_ASYNC16(sA + pf * bufA + (ar0 * LDT + ac0) * 4, A + (size_t)(m0 + ar0) * K + k0 + ac0);
        CP_ASYNC16(sA + pf * bufA + (ar1 * LDT + ac1) * 4, A + (size_t)(m0 + ar1) * K + k0 + ac1);
        CP_ASYNC16(sB + pf * bufB + (br * LDT + bc) * 4,  Wt + (size_t)(n0 + br) * K + k0 + bc);
        CP_COMMIT();
    }

    float c[2][4][4];
    #pragma unroll
    for (int i = 0; i < 2; i++)
        #pragma unroll
        for (int j = 0; j < 4; j++)
            #pragma unroll
            for (int e = 0; e < 4; e++) c[i][j][e] = 0.f;

    for (int kt = 0; kt < nk; kt++) {
        int buf = kt & 1;
        CP_WAIT1();
        __syncthreads();

        const float* as = As[buf];
        const float* bs = Bs[buf];
        #pragma unroll
        for (int ks = 0; ks < 2; ks++) {
            int kb = ks * 8;
            uint32_t a[2][4], b[4][2];
            #pragma unroll
            for (int i = 0; i < 2; i++) {
                int r = wm * 32 + i * 16;
                a[i][0] = __float_as_uint(as[(r + g)     * LDT + kb + tig]);
                a[i][1] = __float_as_uint(as[(r + 8 + g) * LDT + kb + tig]);
                a[i][2] = __float_as_uint(as[(r + g)     * LDT + kb + tig + 4]);
                a[i][3] = __float_as_uint(as[(r + 8 + g) * LDT + kb + tig + 4]);
            }
            #pragma unroll
            for (int j = 0; j < 4; j++) {
                int r = wn * 32 + j * 8 + g;
                b[j][0] = __float_as_uint(bs[r * LDT + kb + tig]);
                b[j][1] = __float_as_uint(bs[r * LDT + kb + tig + 4]);
            }
            #pragma unroll
            for (int i = 0; i < 2; i++)
                #pragma unroll
                for (int j = 0; j < 4; j++)
                    MMA_TF32(c[i][j][0], c[i][j][1], c[i][j][2], c[i][j][3],
                             a[i][0], a[i][1], a[i][2], a[i][3], b[j][0], b[j][1]);
        }
        __syncthreads();
        if (kt + 2 < nk) {
            int k0 = (kt + 2) * 16;
            CP_ASYNC16(sA + buf * bufA + (ar0 * LDT + ac0) * 4, A + (size_t)(m0 + ar0) * K + k0 + ac0);
            CP_ASYNC16(sA + buf * bufA + (ar1 * LDT + ac1) * 4, A + (size_t)(m0 + ar1) * K + k0 + ac1);
            CP_ASYNC16(sB + buf * bufB + (br * LDT + bc) * 4,  Wt + (size_t)(n0 + br) * K + k0 + bc);
        }
        CP_COMMIT();
    }

    #pragma unroll
    for (int i = 0; i < 2; i++) {
        int row0 = m0 + wm * 32 + i * 16 + g;
        #pragma unroll
        for (int j = 0; j < 4; j++) {
            int col = n0 + wn * 32 + j * 8 + 2 * tig;
            float b0 = bias[col], b1 = bias[col + 1];
            #pragma unroll
            for (int half = 0; half < 2; half++) {
                int r = row0 + half * 8;
                float v0 = c[i][j][half * 2 + 0] + b0;
                float v1 = c[i][j][half * 2 + 1] + b1;
                if (EPI == 1) {
                    float2 r2 = *(const float2*)(res + (size_t)r * N + col);
                    v0 += r2.x; v1 += r2.y;
                }
                if (EPI == 2) {
                    v0 = 0.5f * v0 * (1.f + erff(v0 * 0.70710678118654752f));
                    v1 = 0.5f * v1 * (1.f + erff(v1 * 0.70710678118654752f));
                    v0 = f2tf32f(v0); v1 = f2tf32f(v1);
                }
                float2 o; o.x = v0; o.y = v1;
                *(float2*)(C + (size_t)r * N + col) = o;
            }
        }
    }
}

// ---------------- weight transpose (tf32-rounded) ----------------
__global__ __launch_bounds__(256) void transpose_kernel(const float* __restrict__ W,
                                                        float* __restrict__ Wt,
                                                        int K, int N) {
    __shared__ float t[32][33];
    int n0 = blockIdx.x * 32, k0 = blockIdx.y * 32;
    int tx = threadIdx.x, ty = threadIdx.y;
    #pragma unroll
    for (int i = 0; i < 32; i += 8)
        t[ty + i][tx] = W[(size_t)(k0 + ty + i) * N + n0 + tx];
    __syncthreads();
    #pragma unroll
    for (int i = 0; i < 32; i += 8)
        Wt[(size_t)(n0 + ty + i) * K + k0 + tx] = f2tf32f(t[tx][ty + i]);
}

__global__ void concat_bias(const float* __restrict__ a, const float* __restrict__ b,
                            const float* __restrict__ c, float* __restrict__ o) {
    int t = blockIdx.x * 256 + threadIdx.x;
    if (t < 768) o[t] = a[t];
    else if (t < 1536) o[t] = b[t - 768];
    else if (t < 2304) o[t] = c[t - 1536];
}

// ---------------- LayerNorm (tf32-rounded output) ----------------
__global__ __launch_bounds__(256) void ln_kernel(const float* __restrict__ x,
                                                 const float* __restrict__ g,
                                                 const float* __restrict__ b,
                                                 float* __restrict__ out) {
    int row = blockIdx.x;
    const float* xr = x + (size_t)row * DD;
    float s = 0.f, s2 = 0.f;
    for (int i = threadIdx.x; i < DD; i += 256) { float v = xr[i]; s += v; s2 += v * v; }
    #pragma unroll
    for (int o = 16; o > 0; o >>= 1) {
        s  += __shfl_xor_sync(0xffffffffu, s,  o);
        s2 += __shfl_xor_sync(0xffffffffu, s2, o);
    }
    __shared__ float ws[8], ws2[8];
    int w = threadIdx.x >> 5, l = threadIdx.x & 31;
    if (l == 0) { ws[w] = s; ws2[w] = s2; }
    __syncthreads();
    if (w == 0) {
        s  = (l < 8) ? ws[l]  : 0.f;
        s2 = (l < 8) ? ws2[l] : 0.f;
        #pragma unroll
        for (int o = 4; o > 0; o >>= 1) {
            s  += __shfl_xor_sync(0xffffffffu, s,  o);
            s2 += __shfl_xor_sync(0xffffffffu, s2, o);
        }
        if (l == 0) { ws[0] = s; ws2[0] = s2; }
    }
    __syncthreads();
    float mean = ws[0] * (1.f / DD);
    float var  = ws2[0] * (1.f / DD) - mean * mean;
    float inv  = rsqrtf(var + 1e-5f);
    float* orow = out + (size_t)row * DD;
    for (int i = threadIdx.x; i < DD; i += 256)
        orow[i] = f2tf32f((xr[i] - mean) * inv * g[i] + b[i]);
}

// ---------------- temporal bias w/ masks baked in ----------------
__global__ __launch_bounds__(256) void bias_kernel(const float* __restrict__ tm,
                                                   const int* __restrict__ pm,
                                                   const float* __restrict__ t1w,
                                                   const float* __restrict__ t1b,
                                                   const float* __restrict__ t2w,
                                                   const float* __restrict__ t2b) {
    __shared__ float w1[TBN], b1[TBN], w2[TBN];
    int t = threadIdx.x;
    if (t < TBN) { w1[t] = t1w[t]; b1[t] = t1b[t]; w2[t] = t2w[t]; }
    __syncthreads();
    size_t idx = (size_t)blockIdx.x * 256 + t;
    int rem = (int)(idx % (TT * TT));
    int i = rem / TT, j = rem % TT;
    float u = 1.f / logf(E_CONST + tm[idx]);
    float s = t2b[0];
    #pragma unroll
    for (int k = 0; k < TBN; k++) {
        float z = fmaf(u, w1[k], b1[k]);
        z = (z > 0.f) ? z : 0.2f * z;
        s = fmaf(z, w2[k], s);
    }
    bool masked = (pm[idx] == 0) || (j > i && i > 0);
    g_scratch[OF_BIAS + idx] = masked ? NEGV : s;
}

// =======================================================================
// flash attention (fixed): cross-warp row stats via smem exchange.
// one block per (q-tile 64, b*h). 256 thr, 8 warps 4(m) x 2(n).
// =======================================================================
#define SQ_LD 68
#define SV_LD 72
#define FS_Q    0
#define FS_K    (64*68)
#define FS_V    (FS_K + 2*64*68)
#define FS_P    (FS_V + 2*64*72)
#define FS_STAT (FS_P + 64*68)
#define FS_TOT  ((FS_STAT + 256) * 4)

__global__ __launch_bounds__(256, 2) void flash_kernel(const float* __restrict__ qkv,
                                                       float* __restrict__ outA) {
    extern __shared__ float fs[];
    float* sQ = fs + FS_Q;
    float* sK = fs + FS_K;
    float* sV = fs + FS_V;
    float* sP = fs + FS_P;
    float* sMax = fs + FS_STAT;        // [2][64]
    float* sSum = fs + FS_STAT + 128;  // [2][64]
    uint32_t sKu = smem_u32(sK), sVu = smem_u32(sV);

    int tid = threadIdx.x;
    int warp = tid >> 5, lane = tid & 31;
    int wm = warp >> 1, wn = warp & 1;
    int g = lane >> 2, tig = lane & 3;
    int i0 = blockIdx.x * 64;
    int bh = blockIdx.y, b = bh / HH, h = bh % HH;

    const float* base = qkv + (size_t)b * TT * 2304 + h * 64;
    const float* biasB = g_scratch + OF_BIAS + (size_t)b * TT * TT;

    // load Q tile, scale by 1/8, round to tf32
    for (int ch = tid; ch < 1024; ch += 256) {
        int r = ch >> 4, cc = (ch & 15) * 4;
        float4 v = *(const float4*)(base + (size_t)(i0 + r) * 2304 + cc);
        float4 o;
        o.x = f2tf32f(v.x * 0.125f); o.y = f2tf32f(v.y * 0.125f);
        o.z = f2tf32f(v.z * 0.125f); o.w = f2tf32f(v.w * 0.125f);
        *(float4*)(sQ + r * SQ_LD + cc) = o;
    }

    float o[4][4];
    #pragma unroll
    for (int j = 0; j < 4; j++)
        #pragma unroll
        for (int e = 0; e < 4; e++) o[j][e] = 0.f;
    float m0r = -INFINITY, m1r = -INFINITY, l0 = 0.f, l1 = 0.f;

    int ntiles = (i0 == 0) ? (TT / 64) : (i0 >> 6) + 1;
    int rw0 = wm * 16 + g, rw1 = rw0 + 8;   // rows in tile

    // prefetch tile 0
    {
        const float* kb_ = base + 768;
        const float* vb_ = base + 1536;
        for (int ch = tid; ch < 1024; ch += 256) {
            int r = ch >> 4, cc = (ch & 15) * 4;
            CP_ASYNC16(sKu + (r * SQ_LD + cc) * 4, kb_ + (size_t)r * 2304 + cc);
            CP_ASYNC16(sVu + (r * SV_LD + cc) * 4, vb_ + (size_t)r * 2304 + cc);
        }
        CP_COMMIT();
    }

    for (int t = 0; t < ntiles; t++) {
        int j0 = t * 64, buf = t & 1;
        CP_WAIT0();
        __syncthreads();

        // ---- S = Qs @ Ks^T ----
        float c[4][4];
        #pragma unroll
        for (int j = 0; j < 4; j++)
            #pragma unroll
            for (int e = 0; e < 4; e++) c[j][e] = 0.f;
        const float* kS = sK + buf * 64 * SQ_LD;
        #pragma unroll
        for (int kb = 0; kb < 64; kb += 8) {
            uint32_t a[4], bfr[4][2];
            int qr = wm * 16;
            a[0] = __float_as_uint(sQ[(qr + g)     * SQ_LD + kb + tig]);
            a[1] = __float_as_uint(sQ[(qr + 8 + g) * SQ_LD + kb + tig]);
            a[2] = __float_as_uint(sQ[(qr + g)     * SQ_LD + kb + tig + 4]);
            a[3] = __float_as_uint(sQ[(qr + 8 + g) * SQ_LD + kb + tig + 4]);
            #pragma unroll
            for (int j = 0; j < 4; j++) {
                int r = wn * 32 + j * 8 + g;
                bfr[j][0] = __float_as_uint(kS[r * SQ_LD + kb + tig]);
                bfr[j][1] = __float_as_uint(kS[r * SQ_LD + kb + tig + 4]);
            }
            #pragma unroll
            for (int j = 0; j < 4; j++)
                MMA_TF32(c[j][0], c[j][1], c[j][2], c[j][3],
                         a[0], a[1], a[2], a[3], bfr[j][0], bfr[j][1]);
        }

        // ---- bias (+masks) ----
        int gi0 = i0 + rw0, gi1 = i0 + rw1;
        #pragma unroll
        for (int j = 0; j < 4; j++) {
            int gj = j0 + wn * 32 + j * 8 + 2 * tig;
            float2 b0 = *(const float2*)(biasB + (size_t)gi0 * TT + gj);
            float2 b1 = *(const float2*)(biasB + (size_t)gi1 * TT + gj);
            c[j][0] += b0.x; c[j][1] += b0.y;
            c[j][2] += b1.x; c[j][3] += b1.y;
        }

        // ---- per-warp partial row max, exchange across wn pair ----
        float mx0 = c[0][0], mx1 = c[0][2];
        #pragma unroll
        for (int j = 0; j < 4; j++) {
            mx0 = fmaxf(mx0, fmaxf(c[j][0], c[j][1]));
            mx1 = fmaxf(mx1, fmaxf(c[j][2], c[j][3]));
        }
        mx0 = fmaxf(mx0, __shfl_xor_sync(0xffffffffu, mx0, 1));
        mx0 = fmaxf(mx0, __shfl_xor_sync(0xffffffffu, mx0, 2));
        mx1 = fmaxf(mx1, __shfl_xor_sync(0xffffffffu, mx1, 1));
        mx1 = fmaxf(mx1, __shfl_xor_sync(0xffffffffu, mx1, 2));
        if (tig == 0) { sMax[wn * 64 + rw0] = mx0; sMax[wn * 64 + rw1] = mx1; }
        __syncthreads();
        float mxc0 = fmaxf(sMax[rw0], sMax[64 + rw0]);
        float mxc1 = fmaxf(sMax[rw1], sMax[64 + rw1]);

        float mn0 = fmaxf(m0r, mxc0), mn1 = fmaxf(m1r, mxc1);
        float al0 = __expf(m0r - mn0), al1 = __expf(m1r - mn1);

        // ---- exp with combined max, write P, partial sums, exchange ----
        float sum0 = 0.f, sum1 = 0.f;
        #pragma unroll
        for (int j = 0; j < 4; j++) {
            int cw = wn * 32 + j * 8 + 2 * tig;
            float p00 = __expf(c[j][0] - mn0), p01 = __expf(c[j][1] - mn0);
            float p10 = __expf(c[j][2] - mn1), p11 = __expf(c[j][3] - mn1);
            sum0 += p00 + p01; sum1 += p10 + p11;
            float2 q0; q0.x = p00; q0.y = p01;
            float2 q1; q1.x = p10; q1.y = p11;
            *(float2*)(sP + rw0 * SQ_LD + cw) = q0;
            *(float2*)(sP + rw1 * SQ_LD + cw) = q1;
        }
        sum0 += __shfl_xor_sync(0xffffffffu, sum0, 1);
        sum0 += __shfl_xor_sync(0xffffffffu, sum0, 2);
        sum1 += __shfl_xor_sync(0xffffffffu, sum1, 1);
        sum1 += __shfl_xor_sync(0xffffffffu, sum1, 2);
        if (tig == 0) { sSum[wn * 64 + rw0] = sum0; sSum[wn * 64 + rw1] = sum1; }
        __syncthreads();   // P + sums visible; K buffer reads done
        float sc0 = sSum[rw0] + sSum[64 + rw0];
        float sc1 = sSum[rw1] + sSum[64 + rw1];

        l0 = l0 * al0 + sc0;  l1 = l1 * al1 + sc1;
        m0r = mn0;  m1r = mn1;
        #pragma unroll
        for (int j = 0; j < 4; j++) {
            o[j][0] *= al0; o[j][1] *= al0;
            o[j][2] *= al1; o[j][3] *= al1;
        }

        // prefetch next tile into other buffer
        if (t + 1 < ntiles) {
            int nj0 = (t + 1) * 64, nb = buf ^ 1;
            const float* kb_ = base + 768;
            const float* vb_ = base + 1536;
            for (int ch = tid; ch < 1024; ch += 256) {
                int r = ch >> 4, cc = (ch & 15) * 4;
                CP_ASYNC16(sKu + (nb * 64 * SQ_LD + r * SQ_LD + cc) * 4, kb_ + (size_t)(nj0 + r) * 2304 + cc);
                CP_ASYNC16(sVu + (nb * 64 * SV_LD + r * SV_LD + cc) * 4, vb_ + (size_t)(nj0 + r) * 2304 + cc);
            }
            CP_COMMIT();
        }

        // ---- O += P @ V ----
        const float* vS = sV + buf * 64 * SV_LD;
        #pragma unroll
        for (int kb = 0; kb < 64; kb += 8) {
            uint32_t a[4], bfr[4][2];
            int pr = wm * 16;
            a[0] = __float_as_uint(sP[(pr + g)     * SQ_LD + kb + tig]);
            a[1] = __float_as_uint(sP[(pr + 8 + g) * SQ_LD + kb + tig]);
            a[2] = __float_as_uint(sP[(pr + g)     * SQ_LD + kb + tig + 4]);
            a[3] = __float_as_uint(sP[(pr + 8 + g) * SQ_LD + kb + tig + 4]);
            #pragma unroll
            for (int j = 0; j < 4; j++) {
                int nc = wn * 32 + j * 8 + g;
                bfr[j][0] = __float_as_uint(vS[(kb + tig)     * SV_LD + nc]);
                bfr[j][1] = __float_as_uint(vS[(kb + tig + 4) * SV_LD + nc]);
            }
            #pragma unroll
            for (int j = 0; j < 4; j++)
                MMA_TF32(o[j][0], o[j][1], o[j][2], o[j][3],
                         a[0], a[1], a[2], a[3], bfr[j][0], bfr[j][1]);
        }
        __syncthreads();   // sP/sV reusable next iter
    }

    // ---- write O / l ----
    float inv0 = 1.f / l0, inv1 = 1.f / l1;
    int gr0 = b * TT + i0 + wm * 16 + g, gr1 = gr0 + 8;
    #pragma unroll
    for (int j = 0; j < 4; j++) {
        int col = h * 64 + wn * 32 + j * 8 + 2 * tig;
        float2 o0, o1;
        o0.x = f2tf32f(o[j][0] * inv0); o0.y = f2tf32f(o[j][1] * inv0);
        o1.x = f2tf32f(o[j][2] * inv1); o1.y = f2tf32f(o[j][3] * inv1);
        *(float2*)(outA + (size_t)gr0 * DD + col) = o0;
        *(float2*)(outA + (size_t)gr1 * DD + col) = o1;
    }
}

// ---------------- launch ----------------
extern "C" void kernel_launch(void* const* d_in, const int* in_sizes, int n_in,
                              void* d_out, int out_size) {
    const float* x     = (const float*)d_in[0];
    const float* tmat  = (const float*)d_in[1];
    const int*   pm    = (const int*)d_in[2];
    const float* wq = (const float*)d_in[3],  *bq = (const float*)d_in[4];
    const float* wk = (const float*)d_in[5],  *bk = (const float*)d_in[6];
    const float* wv = (const float*)d_in[7],  *bv = (const float*)d_in[8];
    const float* wp = (const float*)d_in[9],  *bp = (const float*)d_in[10];
    const float* t1w = (const float*)d_in[11], *t1b = (const float*)d_in[12];
    const float* t2w = (const float*)d_in[13], *t2b = (const float*)d_in[14];
    const float* f1w = (const float*)d_in[15], *f1b = (const float*)d_in[16];
    const float* f2w = (const float*)d_in[17], *f2b = (const float*)d_in[18];
    const float* ln1g = (const float*)d_in[19], *ln1b = (const float*)d_in[20];
    const float* ln2g = (const float*)d_in[21], *ln2b = (const float*)d_in[22];
    float* out = (float*)d_out;

    float* sc = nullptr;
    cudaGetSymbolAddress((void**)&sc, g_scratch);
    float* gH    = sc + OF_H;
    float* gQKV  = sc + OF_QKV;
    float* gBQKV = sc + OF_BQKV;
    float* gA    = sc + OF_A;
    float* gX2   = sc + OF_X2;
    float* gF    = sc + OF_F;
    float* wcT   = sc + OF_WQT;
    float* wpT   = sc + OF_WPT;
    float* f1T   = sc + OF_F1T;
    float* f2T   = sc + OF_F2T;

    cudaFuncSetAttribute(flash_kernel, cudaFuncAttributeMaxDynamicSharedMemorySize, FS_TOT);

    dim3 tb(32, 8);
    transpose_kernel<<<dim3(DD / 32, DD / 32), tb>>>(wq, wcT, DD, DD);
    transpose_kernel<<<dim3(DD / 32, DD / 32), tb>>>(wk, wcT + 768 * 768, DD, DD);
    transpose_kernel<<<dim3(DD / 32, DD / 32), tb>>>(wv, wcT + 2 * 768 * 768, DD, DD);
    transpose_kernel<<<dim3(DD / 32, DD / 32), tb>>>(wp, wpT, DD, DD);
    transpose_kernel<<<dim3(FFC / 32, DD / 32), tb>>>(f1w, f1T, DD, FFC);
    transpose_kernel<<<dim3(DD / 32, FFC / 32), tb>>>(f2w, f2T, FFC, DD);
    concat_bias<<<9, 256>>>(bq, bk, bv, gBQKV);

    // pre-LN attention
    ln_kernel<<<MROWS, 256>>>(x, ln1g, ln1b, gH);
    gemm_mma<0><<<dim3(2304 / BN, MROWS / BM), 256>>>(gH, wcT, gBQKV, nullptr, gQKV, 2304, DD);

    bias_kernel<<<(BB * TT * TT) / 256, 256>>>(tmat, pm, t1w, t1b, t2w, t2b);
    flash_kernel<<<dim3(TT / 64, BB * HH), 256, FS_TOT>>>(gQKV, gA);

    // out proj + residual
    gemm_mma<1><<<dim3(DD / BN, MROWS / BM), 256>>>(gA, wpT, bp, x, gX2, DD, DD);

    // pre-LN FFN
    ln_kernel<<<MROWS, 256>>>(gX2, ln2g, ln2b, gH);
    gemm_mma<2><<<dim3(FFC / BN, MROWS / BM), 256>>>(gH, f1T, f1b, nullptr, gF, FFC, DD);
    gemm_mma<1><<<dim3(DD / BN, MROWS / BM), 256>>>(gF, f2T, f2b, gX2, out, DD, FFC);
}

// round 6
// speedup vs baseline: 2.6330x; 1.1164x over previous
#include <cuda_runtime.h>
#include <math.h>
#include <stdint.h>

// ---------------- problem constants ----------------
#define BB 4
#define TT 512
#define DD 768
#define HH 12
#define DKC 64
#define FFC 3072
#define TBN 64
#define NEGV (-1e9f)
#define E_CONST 2.718281828459045f
#define MROWS (BB*TT)            // 2048

// ---------------- scratch layout (floats) ----------------
#define OF_H    0ull
#define OF_BIAS 6291456ull                    // biasM with masks baked in (B*T*T)
#define OF_S    7340032ull
#define OF_QKV  OF_S
#define OF_BQKV (OF_S + 4718592ull)           // 2304 floats
#define OF_A    19922944ull
#define OF_X2   21495808ull
#define OF_F    23068672ull
#define OF_WQT  29360128ull                   // combined WqkvT+WpT [4×589824] contiguous
#define OF_WPT  31129600ull
#define OF_F1T  31719424ull
#define OF_F2T  34078720ull
#define SCRATCH_TOTAL 36438016ull

__device__ float g_scratch[SCRATCH_TOTAL];

// ---------------- helpers ----------------
__device__ __forceinline__ uint32_t smem_u32(const void* p) {
    uint32_t a;
    asm("{ .reg .u64 t; cvta.to.shared.u64 t, %1; cvt.u32.u64 %0, t; }" : "=r"(a) : "l"(p));
    return a;
}
__device__ __forceinline__ float f2tf32f(float f) {
    uint32_t r; asm("cvt.rna.tf32.f32 %0, %1;" : "=r"(r) : "f"(f));
    return __uint_as_float(r);
}
#define CP_ASYNC16(dst_u32, src_ptr) \
    asm volatile("cp.async.cg.shared.global [%0], [%1], 16;\n" :: "r"(dst_u32), "l"(__cvta_generic_to_global(src_ptr)))
#define CP_COMMIT() asm volatile("cp.async.commit_group;\n" ::: "memory")
#define CP_WAIT2()  asm volatile("cp.async.wait_group 2;\n" ::: "memory")
#define CP_WAIT0()  asm volatile("cp.async.wait_group 0;\n" ::: "memory")

#define MMA_TF32(c0,c1,c2,c3,a0,a1,a2,a3,b0,b1) \
    asm volatile("mma.sync.aligned.m16n8k8.row.col.f32.tf32.tf32.f32 " \
                 "{%0,%1,%2,%3}, {%4,%5,%6,%7}, {%8,%9}, {%0,%1,%2,%3};\n" \
                 : "+f"(c0), "+f"(c1), "+f"(c2), "+f"(c3) \
                 : "r"(a0), "r"(a1), "r"(a2), "r"(a3), "r"(b0), "r"(b1))

// =======================================================================
// tf32 mma.sync GEMM — 128x64 tile, BK=16, 4-stage cp.async pipeline,
// ONE __syncthreads per K-iteration.
// =======================================================================
#define BM 128
#define BN 64
#define LDT 20
#define GSTAGES 4
#define GEMM_SMEM ((GSTAGES*(BM+BN)*LDT)*4)   // 61440 bytes

template <int EPI>  // 0 bias, 1 bias+res, 2 bias+gelu(+tf32 round)
__global__ __launch_bounds__(256, 2) void gemm_mma(const float* __restrict__ A,
                                                   const float* __restrict__ Wt,
                                                   const float* __restrict__ bias,
                                                   const float* __restrict__ res,
                                                   float* __restrict__ C,
                                                   int N, int K) {
    extern __shared__ float dsm[];
    float* AsBase = dsm;                       // GSTAGES × BM*LDT
    float* BsBase = dsm + GSTAGES * BM * LDT;  // GSTAGES × BN*LDT

    int tid = threadIdx.x;
    int warp = tid >> 5, lane = tid & 31;
    int wm = warp >> 1, wn = warp & 1;
    int g = lane >> 2, tig = lane & 3;
    int m0 = blockIdx.y * BM, n0 = blockIdx.x * BN;

    int ar0 = tid >> 2,            ac0 = (tid & 3) * 4;
    int ar1 = (tid + 256) >> 2,    ac1 = ((tid + 256) & 3) * 4;
    int br  = tid >> 2,            bc  = (tid & 3) * 4;

    uint32_t sA = smem_u32(AsBase);
    uint32_t sB = smem_u32(BsBase);
    const uint32_t bufA = BM * LDT * 4, bufB = BN * LDT * 4;

    const int nk = K >> 4;

    // prefetch stages 0..2
    #pragma unroll
    for (int pf = 0; pf < 3; pf++) {
        int k0 = pf * 16;
        CP_ASYNC16(sA + pf * bufA + (ar0 * LDT + ac0) * 4, A + (size_t)(m0 + ar0) * K + k0 + ac0);
        CP_ASYNC16(sA + pf * bufA + (ar1 * LDT + ac1) * 4, A + (size_t)(m0 + ar1) * K + k0 + ac1);
        CP_ASYNC16(sB + pf * bufB + (br * LDT + bc) * 4,  Wt + (size_t)(n0 + br) * K + k0 + bc);
        CP_COMMIT();
    }

    float c[2][4][4];
    #pragma unroll
    for (int i = 0; i < 2; i++)
        #pragma unroll
        for (int j = 0; j < 4; j++)
            #pragma unroll
            for (int e = 0; e < 4; e++) c[i][j][e] = 0.f;

    for (int kt = 0; kt < nk; kt++) {
        int buf = kt & (GSTAGES - 1);
        CP_WAIT2();          // tile kt resident
        __syncthreads();     // all warps done with stage (kt+3)%4's old contents

        const float* as = AsBase + buf * BM * LDT;
        const float* bs = BsBase + buf * BN * LDT;
        #pragma unroll
        for (int ks = 0; ks < 2; ks++) {
            int kb = ks * 8;
            uint32_t a[2][4], b[4][2];
            #pragma unroll
            for (int i = 0; i < 2; i++) {
                int r = wm * 32 + i * 16;
                a[i][0] = __float_as_uint(as[(r + g)     * LDT + kb + tig]);
                a[i][1] = __float_as_uint(as[(r + 8 + g) * LDT + kb + tig]);
                a[i][2] = __float_as_uint(as[(r + g)     * LDT + kb + tig + 4]);
                a[i][3] = __float_as_uint(as[(r + 8 + g) * LDT + kb + tig + 4]);
            }
            #pragma unroll
            for (int j = 0; j < 4; j++) {
                int r = wn * 32 + j * 8 + g;
                b[j][0] = __float_as_uint(bs[r * LDT + kb + tig]);
                b[j][1] = __float_as_uint(bs[r * LDT + kb + tig + 4]);
            }
            #pragma unroll
            for (int i = 0; i < 2; i++)
                #pragma unroll
                for (int j = 0; j < 4; j++)
                    MMA_TF32(c[i][j][0], c[i][j][1], c[i][j][2], c[i][j][3],
                             a[i][0], a[i][1], a[i][2], a[i][3], b[j][0], b[j][1]);
        }

        if (kt + 3 < nk) {
            int k0 = (kt + 3) * 16;
            int nbuf = (kt + 3) & (GSTAGES - 1);
            CP_ASYNC16(sA + nbuf * bufA + (ar0 * LDT + ac0) * 4, A + (size_t)(m0 + ar0) * K + k0 + ac0);
            CP_ASYNC16(sA + nbuf * bufA + (ar1 * LDT + ac1) * 4, A + (size_t)(m0 + ar1) * K + k0 + ac1);
            CP_ASYNC16(sB + nbuf * bufB + (br * LDT + bc) * 4,  Wt + (size_t)(n0 + br) * K + k0 + bc);
        }
        CP_COMMIT();   // keep group count aligned
    }

    #pragma unroll
    for (int i = 0; i < 2; i++) {
        int row0 = m0 + wm * 32 + i * 16 + g;
        #pragma unroll
        for (int j = 0; j < 4; j++) {
            int col = n0 + wn * 32 + j * 8 + 2 * tig;
            float b0 = bias[col], b1 = bias[col + 1];
            #pragma unroll
            for (int half = 0; half < 2; half++) {
                int r = row0 + half * 8;
                float v0 = c[i][j][half * 2 + 0] + b0;
                float v1 = c[i][j][half * 2 + 1] + b1;
                if (EPI == 1) {
                    float2 r2 = *(const float2*)(res + (size_t)r * N + col);
                    v0 += r2.x; v1 += r2.y;
                }
                if (EPI == 2) {
                    v0 = 0.5f * v0 * (1.f + erff(v0 * 0.70710678118654752f));
                    v1 = 0.5f * v1 * (1.f + erff(v1 * 0.70710678118654752f));
                    v0 = f2tf32f(v0); v1 = f2tf32f(v1);
                }
                float2 o; o.x = v0; o.y = v1;
                *(float2*)(C + (size_t)r * N + col) = o;
            }
        }
    }
}

// ---------------- merged transposes (tf32-rounded) ----------------
// attention weights: wq,wk,wv,wp (all 768x768) -> contiguous dst + z*589824
__global__ __launch_bounds__(256) void transpose_attn(const float* __restrict__ wq,
                                                      const float* __restrict__ wk,
                                                      const float* __restrict__ wv,
                                                      const float* __restrict__ wp,
                                                      float* __restrict__ dst) {
    __shared__ float t[32][33];
    int z = blockIdx.z;
    const float* W = (z == 0) ? wq : (z == 1) ? wk : (z == 2) ? wv : wp;
    float* Wt = dst + (size_t)z * 589824;
    int n0 = blockIdx.x * 32, k0 = blockIdx.y * 32;
    int tx = threadIdx.x, ty = threadIdx.y;
    #pragma unroll
    for (int i = 0; i < 32; i += 8)
        t[ty + i][tx] = W[(size_t)(k0 + ty + i) * DD + n0 + tx];
    __syncthreads();
    #pragma unroll
    for (int i = 0; i < 32; i += 8)
        Wt[(size_t)(n0 + ty + i) * DD + k0 + tx] = f2tf32f(t[tx][ty + i]);
}

// ffn weights: z=0: f1w (K=768,N=3072); z=1: f2w (K=3072,N=768)
__global__ __launch_bounds__(256) void transpose_ffn(const float* __restrict__ f1w,
                                                     float* __restrict__ f1T,
                                                     const float* __restrict__ f2w,
                                                     float* __restrict__ f2T) {
    __shared__ float t[32][33];
    int z = blockIdx.z;
    const float* W; float* Wt; int K, N, n0, k0;
    if (z == 0) { W = f1w; Wt = f1T; K = DD;  N = FFC; n0 = blockIdx.x * 32; k0 = blockIdx.y * 32; }
    else        { W = f2w; Wt = f2T; K = FFC; N = DD;  n0 = blockIdx.y * 32; k0 = blockIdx.x * 32; }
    int tx = threadIdx.x, ty = threadIdx.y;
    #pragma unroll
    for (int i = 0; i < 32; i += 8)
        t[ty + i][tx] = W[(size_t)(k0 + ty + i) * N + n0 + tx];
    __syncthreads();
    #pragma unroll
    for (int i = 0; i < 32; i += 8)
        Wt[(size_t)(n0 + ty + i) * K + k0 + tx] = f2tf32f(t[tx][ty + i]);
}

__global__ void concat_bias(const float* __restrict__ a, const float* __restrict__ b,
                            const float* __restrict__ c, float* __restrict__ o) {
    int t = blockIdx.x * 256 + threadIdx.x;
    if (t < 768) o[t] = a[t];
    else if (t < 1536) o[t] = b[t - 768];
    else if (t < 2304) o[t] = c[t - 1536];
}

// ---------------- LayerNorm (tf32-rounded output) ----------------
__global__ __launch_bounds__(256) void ln_kernel(const float* __restrict__ x,
                                                 const float* __restrict__ g,
                                                 const float* __restrict__ b,
                                                 float* __restrict__ out) {
    int row = blockIdx.x;
    const float* xr = x + (size_t)row * DD;
    float s = 0.f, s2 = 0.f;
    for (int i = threadIdx.x; i < DD; i += 256) { float v = xr[i]; s += v; s2 += v * v; }
    #pragma unroll
    for (int o = 16; o > 0; o >>= 1) {
        s  += __shfl_xor_sync(0xffffffffu, s,  o);
        s2 += __shfl_xor_sync(0xffffffffu, s2, o);
    }
    __shared__ float ws[8], ws2[8];
    int w = threadIdx.x >> 5, l = threadIdx.x & 31;
    if (l == 0) { ws[w] = s; ws2[w] = s2; }
    __syncthreads();
    if (w == 0) {
        s  = (l < 8) ? ws[l]  : 0.f;
        s2 = (l < 8) ? ws2[l] : 0.f;
        #pragma unroll
        for (int o = 4; o > 0; o >>= 1) {
            s  += __shfl_xor_sync(0xffffffffu, s,  o);
            s2 += __shfl_xor_sync(0xffffffffu, s2, o);
        }
        if (l == 0) { ws[0] = s; ws2[0] = s2; }
    }
    __syncthreads();
    float mean = ws[0] * (1.f / DD);
    float var  = ws2[0] * (1.f / DD) - mean * mean;
    float inv  = rsqrtf(var + 1e-5f);
    float* orow = out + (size_t)row * DD;
    for (int i = threadIdx.x; i < DD; i += 256)
        orow[i] = f2tf32f((xr[i] - mean) * inv * g[i] + b[i]);
}

// ---------------- temporal bias w/ masks baked in ----------------
__global__ __launch_bounds__(256) void bias_kernel(const float* __restrict__ tm,
                                                   const int* __restrict__ pm,
                                                   const float* __restrict__ t1w,
                                                   const float* __restrict__ t1b,
                                                   const float* __restrict__ t2w,
                                                   const float* __restrict__ t2b) {
    __shared__ float w1[TBN], b1[TBN], w2[TBN];
    int t = threadIdx.x;
    if (t < TBN) { w1[t] = t1w[t]; b1[t] = t1b[t]; w2[t] = t2w[t]; }
    __syncthreads();
    size_t idx = (size_t)blockIdx.x * 256 + t;
    int rem = (int)(idx % (TT * TT));
    int i = rem / TT, j = rem % TT;
    float u = 1.f / logf(E_CONST + tm[idx]);
    float s = t2b[0];
    #pragma unroll
    for (int k = 0; k < TBN; k++) {
        float z = fmaf(u, w1[k], b1[k]);
        z = (z > 0.f) ? z : 0.2f * z;
        s = fmaf(z, w2[k], s);
    }
    bool masked = (pm[idx] == 0) || (j > i && i > 0);
    g_scratch[OF_BIAS + idx] = masked ? NEGV : s;
}

// =======================================================================
// flash attention (validated in R5) — unchanged
// =======================================================================
#define SQ_LD 68
#define SV_LD 72
#define FS_Q    0
#define FS_K    (64*68)
#define FS_V    (FS_K + 2*64*68)
#define FS_P    (FS_V + 2*64*72)
#define FS_STAT (FS_P + 64*68)
#define FS_TOT  ((FS_STAT + 256) * 4)

__global__ __launch_bounds__(256, 2) void flash_kernel(const float* __restrict__ qkv,
                                                       float* __restrict__ outA) {
    extern __shared__ float fs[];
    float* sQ = fs + FS_Q;
    float* sK = fs + FS_K;
    float* sV = fs + FS_V;
    float* sP = fs + FS_P;
    float* sMax = fs + FS_STAT;
    float* sSum = fs + FS_STAT + 128;
    uint32_t sKu = smem_u32(sK), sVu = smem_u32(sV);

    int tid = threadIdx.x;
    int warp = tid >> 5, lane = tid & 31;
    int wm = warp >> 1, wn = warp & 1;
    int g = lane >> 2, tig = lane & 3;
    int i0 = blockIdx.x * 64;
    int bh = blockIdx.y, b = bh / HH, h = bh % HH;

    const float* base = qkv + (size_t)b * TT * 2304 + h * 64;
    const float* biasB = g_scratch + OF_BIAS + (size_t)b * TT * TT;

    for (int ch = tid; ch < 1024; ch += 256) {
        int r = ch >> 4, cc = (ch & 15) * 4;
        float4 v = *(const float4*)(base + (size_t)(i0 + r) * 2304 + cc);
        float4 o;
        o.x = f2tf32f(v.x * 0.125f); o.y = f2tf32f(v.y * 0.125f);
        o.z = f2tf32f(v.z * 0.125f); o.w = f2tf32f(v.w * 0.125f);
        *(float4*)(sQ + r * SQ_LD + cc) = o;
    }

    float o[4][4];
    #pragma unroll
    for (int j = 0; j < 4; j++)
        #pragma unroll
        for (int e = 0; e < 4; e++) o[j][e] = 0.f;
    float m0r = -INFINITY, m1r = -INFINITY, l0 = 0.f, l1 = 0.f;

    int ntiles = (i0 == 0) ? (TT / 64) : (i0 >> 6) + 1;
    int rw0 = wm * 16 + g, rw1 = rw0 + 8;

    {
        const float* kb_ = base + 768;
        const float* vb_ = base + 1536;
        for (int ch = tid; ch < 1024; ch += 256) {
            int r = ch >> 4, cc = (ch & 15) * 4;
            CP_ASYNC16(sKu + (r * SQ_LD + cc) * 4, kb_ + (size_t)r * 2304 + cc);
            CP_ASYNC16(sVu + (r * SV_LD + cc) * 4, vb_ + (size_t)r * 2304 + cc);
        }
        CP_COMMIT();
    }

    for (int t = 0; t < ntiles; t++) {
        int j0 = t * 64, buf = t & 1;
        CP_WAIT0();
        __syncthreads();

        float c[4][4];
        #pragma unroll
        for (int j = 0; j < 4; j++)
            #pragma unroll
            for (int e = 0; e < 4; e++) c[j][e] = 0.f;
        const float* kS = sK + buf * 64 * SQ_LD;
        #pragma unroll
        for (int kb = 0; kb < 64; kb += 8) {
            uint32_t a[4], bfr[4][2];
            int qr = wm * 16;
            a[0] = __float_as_uint(sQ[(qr + g)     * SQ_LD + kb + tig]);
            a[1] = __float_as_uint(sQ[(qr + 8 + g) * SQ_LD + kb + tig]);
            a[2] = __float_as_uint(sQ[(qr + g)     * SQ_LD + kb + tig + 4]);
            a[3] = __float_as_uint(sQ[(qr + 8 + g) * SQ_LD + kb + tig + 4]);
            #pragma unroll
            for (int j = 0; j < 4; j++) {
                int r = wn * 32 + j * 8 + g;
                bfr[j][0] = __float_as_uint(kS[r * SQ_LD + kb + tig]);
                bfr[j][1] = __float_as_uint(kS[r * SQ_LD + kb + tig + 4]);
            }
            #pragma unroll
            for (int j = 0; j < 4; j++)
                MMA_TF32(c[j][0], c[j][1], c[j][2], c[j][3],
                         a[0], a[1], a[2], a[3], bfr[j][0], bfr[j][1]);
        }

        int gi0 = i0 + rw0, gi1 = i0 + rw1;
        #pragma unroll
        for (int j = 0; j < 4; j++) {
            int gj = j0 + wn * 32 + j * 8 + 2 * tig;
            float2 b0 = *(const float2*)(biasB + (size_t)gi0 * TT + gj);
            float2 b1 = *(const float2*)(biasB + (size_t)gi1 * TT + gj);
            c[j][0] += b0.x; c[j][1] += b0.y;
            c[j][2] += b1.x; c[j][3] += b1.y;
        }

        float mx0 = c[0][0], mx1 = c[0][2];
        #pragma unroll
        for (int j = 0; j < 4; j++) {
            mx0 = fmaxf(mx0, fmaxf(c[j][0], c[j][1]));
            mx1 = fmaxf(mx1, fmaxf(c[j][2], c[j][3]));
        }
        mx0 = fmaxf(mx0, __shfl_xor_sync(0xffffffffu, mx0, 1));
        mx0 = fmaxf(mx0, __shfl_xor_sync(0xffffffffu, mx0, 2));
        mx1 = fmaxf(mx1, __shfl_xor_sync(0xffffffffu, mx1, 1));
        mx1 = fmaxf(mx1, __shfl_xor_sync(0xffffffffu, mx1, 2));
        if (tig == 0) { sMax[wn * 64 + rw0] = mx0; sMax[wn * 64 + rw1] = mx1; }
        __syncthreads();
        float mxc0 = fmaxf(sMax[rw0], sMax[64 + rw0]);
        float mxc1 = fmaxf(sMax[rw1], sMax[64 + rw1]);

        float mn0 = fmaxf(m0r, mxc0), mn1 = fmaxf(m1r, mxc1);
        float al0 = __expf(m0r - mn0), al1 = __expf(m1r - mn1);

        float sum0 = 0.f, sum1 = 0.f;
        #pragma unroll
        for (int j = 0; j < 4; j++) {
            int cw = wn * 32 + j * 8 + 2 * tig;
            float p00 = __expf(c[j][0] - mn0), p01 = __expf(c[j][1] - mn0);
            float p10 = __expf(c[j][2] - mn1), p11 = __expf(c[j][3] - mn1);
            sum0 += p00 + p01; sum1 += p10 + p11;
            float2 q0; q0.x = p00; q0.y = p01;
            float2 q1; q1.x = p10; q1.y = p11;
            *(float2*)(sP + rw0 * SQ_LD + cw) = q0;
            *(float2*)(sP + rw1 * SQ_LD + cw) = q1;
        }
        sum0 += __shfl_xor_sync(0xffffffffu, sum0, 1);
        sum0 += __shfl_xor_sync(0xffffffffu, sum0, 2);
        sum1 += __shfl_xor_sync(0xffffffffu, sum1, 1);
        sum1 += __shfl_xor_sync(0xffffffffu, sum1, 2);
        if (tig == 0) { sSum[wn * 64 + rw0] = sum0; sSum[wn * 64 + rw1] = sum1; }
        __syncthreads();
        float sc0 = sSum[rw0] + sSum[64 + rw0];
        float sc1 = sSum[rw1] + sSum[64 + rw1];

        l0 = l0 * al0 + sc0;  l1 = l1 * al1 + sc1;
        m0r = mn0;  m1r = mn1;
        #pragma unroll
        for (int j = 0; j < 4; j++) {
            o[j][0] *= al0; o[j][1] *= al0;
            o[j][2] *= al1; o[j][3] *= al1;
        }

        if (t + 1 < ntiles) {
            int nj0 = (t + 1) * 64, nb = buf ^ 1;
            const float* kb_ = base + 768;
            const float* vb_ = base + 1536;
            for (int ch = tid; ch < 1024; ch += 256) {
                int r = ch >> 4, cc = (ch & 15) * 4;
                CP_ASYNC16(sKu + (nb * 64 * SQ_LD + r * SQ_LD + cc) * 4, kb_ + (size_t)(nj0 + r) * 2304 + cc);
                CP_ASYNC16(sVu + (nb * 64 * SV_LD + r * SV_LD + cc) * 4, vb_ + (size_t)(nj0 + r) * 2304 + cc);
            }
            CP_COMMIT();
        }

        const float* vS = sV + buf * 64 * SV_LD;
        #pragma unroll
        for (int kb = 0; kb < 64; kb += 8) {
            uint32_t a[4], bfr[4][2];
            int pr = wm * 16;
            a[0] = __float_as_uint(sP[(pr + g)     * SQ_LD + kb + tig]);
            a[1] = __float_as_uint(sP[(pr + 8 + g) * SQ_LD + kb + tig]);
            a[2] = __float_as_uint(sP[(pr + g)     * SQ_LD + kb + tig + 4]);
            a[3] = __float_as_uint(sP[(pr + 8 + g) * SQ_LD + kb + tig + 4]);
            #pragma unroll
            for (int j = 0; j < 4; j++) {
                int nc = wn * 32 + j * 8 + g;
                bfr[j][0] = __float_as_uint(vS[(kb + tig)     * SV_LD + nc]);
                bfr[j][1] = __float_as_uint(vS[(kb + tig + 4) * SV_LD + nc]);
            }
            #pragma unroll
            for (int j = 0; j < 4; j++)
                MMA_TF32(o[j][0], o[j][1], o[j][2], o[j][3],
                         a[0], a[1], a[2], a[3], bfr[j][0], bfr[j][1]);
        }
        __syncthreads();
    }

    float inv0 = 1.f / l0, inv1 = 1.f / l1;
    int gr0 = b * TT + i0 + wm * 16 + g, gr1 = gr0 + 8;
    #pragma unroll
    for (int j = 0; j < 4; j++) {
        int col = h * 64 + wn * 32 + j * 8 + 2 * tig;
        float2 o0, o1;
        o0.x = f2tf32f(o[j][0] * inv0); o0.y = f2tf32f(o[j][1] * inv0);
        o1.x = f2tf32f(o[j][2] * inv1); o1.y = f2tf32f(o[j][3] * inv1);
        *(float2*)(outA + (size_t)gr0 * DD + col) = o0;
        *(float2*)(outA + (size_t)gr1 * DD + col) = o1;
    }
}

// ---------------- launch ----------------
extern "C" void kernel_launch(void* const* d_in, const int* in_sizes, int n_in,
                              void* d_out, int out_size) {
    const float* x     = (const float*)d_in[0];
    const float* tmat  = (const float*)d_in[1];
    const int*   pm    = (const int*)d_in[2];
    const float* wq = (const float*)d_in[3],  *bq = (const float*)d_in[4];
    const float* wk = (const float*)d_in[5],  *bk = (const float*)d_in[6];
    const float* wv = (const float*)d_in[7],  *bv = (const float*)d_in[8];
    const float* wp = (const float*)d_in[9],  *bp = (const float*)d_in[10];
    const float* t1w = (const float*)d_in[11], *t1b = (const float*)d_in[12];
    const float* t2w = (const float*)d_in[13], *t2b = (const float*)d_in[14];
    const float* f1w = (const float*)d_in[15], *f1b = (const float*)d_in[16];
    const float* f2w = (const float*)d_in[17], *f2b = (const float*)d_in[18];
    const float* ln1g = (const float*)d_in[19], *ln1b = (const float*)d_in[20];
    const float* ln2g = (const float*)d_in[21], *ln2b = (const float*)d_in[22];
    float* out = (float*)d_out;

    float* sc = nullptr;
    cudaGetSymbolAddress((void**)&sc, g_scratch);
    float* gH    = sc + OF_H;
    float* gQKV  = sc + OF_QKV;
    float* gBQKV = sc + OF_BQKV;
    float* gA    = sc + OF_A;
    float* gX2   = sc + OF_X2;
    float* gF    = sc + OF_F;
    float* wcT   = sc + OF_WQT;
    float* wpT   = sc + OF_WPT;
    float* f1T   = sc + OF_F1T;
    float* f2T   = sc + OF_F2T;

    cudaFuncSetAttribute(gemm_mma<0>, cudaFuncAttributeMaxDynamicSharedMemorySize, GEMM_SMEM);
    cudaFuncSetAttribute(gemm_mma<1>, cudaFuncAttributeMaxDynamicSharedMemorySize, GEMM_SMEM);
    cudaFuncSetAttribute(gemm_mma<2>, cudaFuncAttributeMaxDynamicSharedMemorySize, GEMM_SMEM);
    cudaFuncSetAttribute(flash_kernel, cudaFuncAttributeMaxDynamicSharedMemorySize, FS_TOT);

    dim3 tb(32, 8);
    // launch indices 0..4 before the QKV GEMM so ncu (-s 5 -c 1) profiles it
    transpose_attn<<<dim3(24, 24, 4), tb>>>(wq, wk, wv, wp, wcT);          // 0
    transpose_ffn<<<dim3(96, 24, 2), tb>>>(f1w, f1T, f2w, f2T);            // 1
    concat_bias<<<9, 256>>>(bq, bk, bv, gBQKV);                            // 2
    bias_kernel<<<(BB * TT * TT) / 256, 256>>>(tmat, pm, t1w, t1b, t2w, t2b); // 3
    ln_kernel<<<MROWS, 256>>>(x, ln1g, ln1b, gH);                          // 4

    gemm_mma<0><<<dim3(2304 / BN, MROWS / BM), 256, GEMM_SMEM>>>(gH, wcT, gBQKV, nullptr, gQKV, 2304, DD); // 5

    flash_kernel<<<dim3(TT / 64, BB * HH), 256, FS_TOT>>>(gQKV, gA);

    gemm_mma<1><<<dim3(DD / BN, MROWS / BM), 256, GEMM_SMEM>>>(gA, wpT, bp, x, gX2, DD, DD);

    ln_kernel<<<MROWS, 256>>>(gX2, ln2g, ln2b, gH);
    gemm_mma<2><<<dim3(FFC / BN, MROWS / BM), 256, GEMM_SMEM>>>(gH, f1T, f1b, nullptr, gF, FFC, DD);
    gemm_mma<1><<<dim3(DD / BN, MROWS / BM), 256, GEMM_SMEM>>>(gF, f2T, f2b, gX2, out, DD, FFC);
}

// round 7
// speedup vs baseline: 2.7768x; 1.0546x over previous
#include <cuda_runtime.h>
#include <math.h>
#include <stdint.h>

// ---------------- problem constants ----------------
#define BB 4
#define TT 512
#define DD 768
#define HH 12
#define DKC 64
#define FFC 3072
#define TBN 64
#define NEGV (-1e9f)
#define E_CONST 2.718281828459045f
#define MROWS (BB*TT)            // 2048

// ---------------- scratch layout (floats) ----------------
#define OF_H    0ull
#define OF_BIAS 6291456ull                    // biasM with masks baked in (B*T*T)
#define OF_S    7340032ull
#define OF_QKV  OF_S
#define OF_BQKV (OF_S + 4718592ull)           // 2304 floats
#define OF_A    19922944ull
#define OF_X2   21495808ull
#define OF_F    23068672ull
#define OF_WQT  29360128ull                   // combined WqkvT+WpT [4×589824] contiguous
#define OF_WPT  31129600ull
#define OF_F1T  31719424ull
#define OF_F2T  34078720ull
#define SCRATCH_TOTAL 36438016ull

__device__ float g_scratch[SCRATCH_TOTAL];

// ---------------- helpers ----------------
__device__ __forceinline__ uint32_t smem_u32(const void* p) {
    uint32_t a;
    asm("{ .reg .u64 t; cvta.to.shared.u64 t, %1; cvt.u32.u64 %0, t; }" : "=r"(a) : "l"(p));
    return a;
}
__device__ __forceinline__ float f2tf32f(float f) {
    uint32_t r; asm("cvt.rna.tf32.f32 %0, %1;" : "=r"(r) : "f"(f));
    return __uint_as_float(r);
}
#define CP_ASYNC16(dst_u32, src_ptr) \
    asm volatile("cp.async.cg.shared.global [%0], [%1], 16;\n" :: "r"(dst_u32), "l"(__cvta_generic_to_global(src_ptr)))
#define CP_COMMIT() asm volatile("cp.async.commit_group;\n" ::: "memory")
#define CP_WAIT2()  asm volatile("cp.async.wait_group 2;\n" ::: "memory")
#define CP_WAIT0()  asm volatile("cp.async.wait_group 0;\n" ::: "memory")

#define MMA_TF32(c0,c1,c2,c3,a0,a1,a2,a3,b0,b1) \
    asm volatile("mma.sync.aligned.m16n8k8.row.col.f32.tf32.tf32.f32 " \
                 "{%0,%1,%2,%3}, {%4,%5,%6,%7}, {%8,%9}, {%0,%1,%2,%3};\n" \
                 : "+f"(c0), "+f"(c1), "+f"(c2), "+f"(c3) \
                 : "r"(a0), "r"(a1), "r"(a2), "r"(a3), "r"(b0), "r"(b1))

#define LDSM_X4(d0,d1,d2,d3,addr) \
    asm volatile("ldmatrix.sync.aligned.m8n8.x4.shared.b16 {%0,%1,%2,%3}, [%4];\n" \
                 : "=r"(d0), "=r"(d1), "=r"(d2), "=r"(d3) : "r"(addr))

// =======================================================================
// tf32 mma.sync GEMM — 128x64 tile, BK=16, 4-stage cp.async pipeline,
// ldmatrix.b16 fragment loads (bit-identical to scalar path, 4x fewer ops)
// =======================================================================
#define BM 128
#define BN 64
#define LDT 20
#define GSTAGES 4
#define GEMM_SMEM ((GSTAGES*(BM+BN)*LDT)*4)   // 61440 bytes

template <int EPI>  // 0 bias, 1 bias+res, 2 bias+gelu(+tf32 round)
__global__ __launch_bounds__(256, 2) void gemm_mma(const float* __restrict__ A,
                                                   const float* __restrict__ Wt,
                                                   const float* __restrict__ bias,
                                                   const float* __restrict__ res,
                                                   float* __restrict__ C,
                                                   int N, int K) {
    extern __shared__ float dsm[];
    float* AsBase = dsm;                       // GSTAGES × BM*LDT
    float* BsBase = dsm + GSTAGES * BM * LDT;  // GSTAGES × BN*LDT

    int tid = threadIdx.x;
    int warp = tid >> 5, lane = tid & 31;
    int wm = warp >> 1, wn = warp & 1;
    int g = lane >> 2, tig = lane & 3;
    int m0 = blockIdx.y * BM, n0 = blockIdx.x * BN;

    int ar0 = tid >> 2,            ac0 = (tid & 3) * 4;
    int ar1 = (tid + 256) >> 2,    ac1 = ((tid + 256) & 3) * 4;
    int br  = tid >> 2,            bc  = (tid & 3) * 4;

    uint32_t sA = smem_u32(AsBase);
    uint32_t sB = smem_u32(BsBase);
    const uint32_t bufA = BM * LDT * 4, bufB = BN * LDT * 4;

    // ldmatrix per-thread address offsets (floats)
    int q = lane >> 3, l7 = lane & 7;
    int a_row = wm * 32 + (q & 1) * 8 + l7,  a_col = (q >> 1) * 4;   // + i*16 rows, + kb cols
    int b_row = wn * 32 + (q >> 1) * 8 + l7, b_col = (q & 1) * 4;    // + p*16 rows, + kb cols
    uint32_t aAddr0 = sA + (uint32_t)(a_row * LDT + a_col) * 4;
    uint32_t bAddr0 = sB + (uint32_t)(b_row * LDT + b_col) * 4;

    const int nk = K >> 4;

    // prefetch stages 0..2
    #pragma unroll
    for (int pf = 0; pf < 3; pf++) {
        int k0 = pf * 16;
        CP_ASYNC16(sA + pf * bufA + (ar0 * LDT + ac0) * 4, A + (size_t)(m0 + ar0) * K + k0 + ac0);
        CP_ASYNC16(sA + pf * bufA + (ar1 * LDT + ac1) * 4, A + (size_t)(m0 + ar1) * K + k0 + ac1);
        CP_ASYNC16(sB + pf * bufB + (br * LDT + bc) * 4,  Wt + (size_t)(n0 + br) * K + k0 + bc);
        CP_COMMIT();
    }

    float c[2][4][4];
    #pragma unroll
    for (int i = 0; i < 2; i++)
        #pragma unroll
        for (int j = 0; j < 4; j++)
            #pragma unroll
            for (int e = 0; e < 4; e++) c[i][j][e] = 0.f;

    for (int kt = 0; kt < nk; kt++) {
        int buf = kt & (GSTAGES - 1);
        CP_WAIT2();
        __syncthreads();

        uint32_t aBuf = aAddr0 + buf * bufA;
        uint32_t bBuf = bAddr0 + buf * bufB;
        #pragma unroll
        for (int ks = 0; ks < 2; ks++) {
            uint32_t kOff = (uint32_t)(ks * 8) * 4;   // kb floats -> bytes
            uint32_t a[2][4], b[4][2];
            #pragma unroll
            for (int i = 0; i < 2; i++)
                LDSM_X4(a[i][0], a[i][1], a[i][2], a[i][3],
                        aBuf + (uint32_t)(i * 16 * LDT) * 4 + kOff);
            #pragma unroll
            for (int p = 0; p < 2; p++)
                LDSM_X4(b[2*p][0], b[2*p][1], b[2*p+1][0], b[2*p+1][1],
                        bBuf + (uint32_t)(p * 16 * LDT) * 4 + kOff);
            #pragma unroll
            for (int i = 0; i < 2; i++)
                #pragma unroll
                for (int j = 0; j < 4; j++)
                    MMA_TF32(c[i][j][0], c[i][j][1], c[i][j][2], c[i][j][3],
                             a[i][0], a[i][1], a[i][2], a[i][3], b[j][0], b[j][1]);
        }

        if (kt + 3 < nk) {
            int k0 = (kt + 3) * 16;
            int nbuf = (kt + 3) & (GSTAGES - 1);
            CP_ASYNC16(sA + nbuf * bufA + (ar0 * LDT + ac0) * 4, A + (size_t)(m0 + ar0) * K + k0 + ac0);
            CP_ASYNC16(sA + nbuf * bufA + (ar1 * LDT + ac1) * 4, A + (size_t)(m0 + ar1) * K + k0 + ac1);
            CP_ASYNC16(sB + nbuf * bufB + (br * LDT + bc) * 4,  Wt + (size_t)(n0 + br) * K + k0 + bc);
        }
        CP_COMMIT();
    }

    #pragma unroll
    for (int i = 0; i < 2; i++) {
        int row0 = m0 + wm * 32 + i * 16 + g;
        #pragma unroll
        for (int j = 0; j < 4; j++) {
            int col = n0 + wn * 32 + j * 8 + 2 * tig;
            float b0 = bias[col], b1 = bias[col + 1];
            #pragma unroll
            for (int half = 0; half < 2; half++) {
                int r = row0 + half * 8;
                float v0 = c[i][j][half * 2 + 0] + b0;
                float v1 = c[i][j][half * 2 + 1] + b1;
                if (EPI == 1) {
                    float2 r2 = *(const float2*)(res + (size_t)r * N + col);
                    v0 += r2.x; v1 += r2.y;
                }
                if (EPI == 2) {
                    v0 = 0.5f * v0 * (1.f + erff(v0 * 0.70710678118654752f));
                    v1 = 0.5f * v1 * (1.f + erff(v1 * 0.70710678118654752f));
                    v0 = f2tf32f(v0); v1 = f2tf32f(v1);
                }
                float2 o; o.x = v0; o.y = v1;
                *(float2*)(C + (size_t)r * N + col) = o;
            }
        }
    }
}

// ---------------- merged transposes (tf32-rounded) ----------------
__global__ __launch_bounds__(256) void transpose_attn(const float* __restrict__ wq,
                                                      const float* __restrict__ wk,
                                                      const float* __restrict__ wv,
                                                      const float* __restrict__ wp,
                                                      float* __restrict__ dst) {
    __shared__ float t[32][33];
    int z = blockIdx.z;
    const float* W = (z == 0) ? wq : (z == 1) ? wk : (z == 2) ? wv : wp;
    float* Wt = dst + (size_t)z * 589824;
    int n0 = blockIdx.x * 32, k0 = blockIdx.y * 32;
    int tx = threadIdx.x, ty = threadIdx.y;
    #pragma unroll
    for (int i = 0; i < 32; i += 8)
        t[ty + i][tx] = W[(size_t)(k0 + ty + i) * DD + n0 + tx];
    __syncthreads();
    #pragma unroll
    for (int i = 0; i < 32; i += 8)
        Wt[(size_t)(n0 + ty + i) * DD + k0 + tx] = f2tf32f(t[tx][ty + i]);
}

__global__ __launch_bounds__(256) void transpose_ffn(const float* __restrict__ f1w,
                                                     float* __restrict__ f1T,
                                                     const float* __restrict__ f2w,
                                                     float* __restrict__ f2T) {
    __shared__ float t[32][33];
    int z = blockIdx.z;
    const float* W; float* Wt; int K, N, n0, k0;
    if (z == 0) { W = f1w; Wt = f1T; K = DD;  N = FFC; n0 = blockIdx.x * 32; k0 = blockIdx.y * 32; }
    else        { W = f2w; Wt = f2T; K = FFC; N = DD;  n0 = blockIdx.y * 32; k0 = blockIdx.x * 32; }
    int tx = threadIdx.x, ty = threadIdx.y;
    #pragma unroll
    for (int i = 0; i < 32; i += 8)
        t[ty + i][tx] = W[(size_t)(k0 + ty + i) * N + n0 + tx];
    __syncthreads();
    #pragma unroll
    for (int i = 0; i < 32; i += 8)
        Wt[(size_t)(n0 + ty + i) * K + k0 + tx] = f2tf32f(t[tx][ty + i]);
}

__global__ void concat_bias(const float* __restrict__ a, const float* __restrict__ b,
                            const float* __restrict__ c, float* __restrict__ o) {
    int t = blockIdx.x * 256 + threadIdx.x;
    if (t < 768) o[t] = a[t];
    else if (t < 1536) o[t] = b[t - 768];
    else if (t < 2304) o[t] = c[t - 1536];
}

// ---------------- LayerNorm (tf32-rounded output) ----------------
__global__ __launch_bounds__(256) void ln_kernel(const float* __restrict__ x,
                                                 const float* __restrict__ g,
                                                 const float* __restrict__ b,
                                                 float* __restrict__ out) {
    int row = blockIdx.x;
    const float* xr = x + (size_t)row * DD;
    float s = 0.f, s2 = 0.f;
    for (int i = threadIdx.x; i < DD; i += 256) { float v = xr[i]; s += v; s2 += v * v; }
    #pragma unroll
    for (int o = 16; o > 0; o >>= 1) {
        s  += __shfl_xor_sync(0xffffffffu, s,  o);
        s2 += __shfl_xor_sync(0xffffffffu, s2, o);
    }
    __shared__ float ws[8], ws2[8];
    int w = threadIdx.x >> 5, l = threadIdx.x & 31;
    if (l == 0) { ws[w] = s; ws2[w] = s2; }
    __syncthreads();
    if (w == 0) {
        s  = (l < 8) ? ws[l]  : 0.f;
        s2 = (l < 8) ? ws2[l] : 0.f;
        #pragma unroll
        for (int o = 4; o > 0; o >>= 1) {
            s  += __shfl_xor_sync(0xffffffffu, s,  o);
            s2 += __shfl_xor_sync(0xffffffffu, s2, o);
        }
        if (l == 0) { ws[0] = s; ws2[0] = s2; }
    }
    __syncthreads();
    float mean = ws[0] * (1.f / DD);
    float var  = ws2[0] * (1.f / DD) - mean * mean;
    float inv  = rsqrtf(var + 1e-5f);
    float* orow = out + (size_t)row * DD;
    for (int i = threadIdx.x; i < DD; i += 256)
        orow[i] = f2tf32f((xr[i] - mean) * inv * g[i] + b[i]);
}

// ---------------- temporal bias w/ masks baked in (fast math) ----------------
__global__ __launch_bounds__(256) void bias_kernel(const float* __restrict__ tm,
                                                   const int* __restrict__ pm,
                                                   const float* __restrict__ t1w,
                                                   const float* __restrict__ t1b,
                                                   const float* __restrict__ t2w,
                                                   const float* __restrict__ t2b) {
    __shared__ float w1[TBN], b1[TBN], w2[TBN];
    int t = threadIdx.x;
    if (t < TBN) { w1[t] = t1w[t]; b1[t] = t1b[t]; w2[t] = t2w[t]; }
    __syncthreads();
    size_t idx = (size_t)blockIdx.x * 256 + t;
    int rem = (int)(idx % (TT * TT));
    int i = rem / TT, j = rem % TT;
    float u = __fdividef(1.f, __logf(E_CONST + tm[idx]));
    float s = t2b[0];
    #pragma unroll
    for (int k = 0; k < TBN; k++) {
        float z = fmaf(u, w1[k], b1[k]);
        z = (z > 0.f) ? z : 0.2f * z;
        s = fmaf(z, w2[k], s);
    }
    bool masked = (pm[idx] == 0) || (j > i && i > 0);
    g_scratch[OF_BIAS + idx] = masked ? NEGV : s;
}

// =======================================================================
// flash attention (validated in R5) — unchanged
// =======================================================================
#define SQ_LD 68
#define SV_LD 72
#define FS_Q    0
#define FS_K    (64*68)
#define FS_V    (FS_K + 2*64*68)
#define FS_P    (FS_V + 2*64*72)
#define FS_STAT (FS_P + 64*68)
#define FS_TOT  ((FS_STAT + 256) * 4)

__global__ __launch_bounds__(256, 2) void flash_kernel(const float* __restrict__ qkv,
                                                       float* __restrict__ outA) {
    extern __shared__ float fs[];
    float* sQ = fs + FS_Q;
    float* sK = fs + FS_K;
    float* sV = fs + FS_V;
    float* sP = fs + FS_P;
    float* sMax = fs + FS_STAT;
    float* sSum = fs + FS_STAT + 128;
    uint32_t sKu = smem_u32(sK), sVu = smem_u32(sV);

    int tid = threadIdx.x;
    int warp = tid >> 5, lane = tid & 31;
    int wm = warp >> 1, wn = warp & 1;
    int g = lane >> 2, tig = lane & 3;
    int i0 = blockIdx.x * 64;
    int bh = blockIdx.y, b = bh / HH, h = bh % HH;

    const float* base = qkv + (size_t)b * TT * 2304 + h * 64;
    const float* biasB = g_scratch + OF_BIAS + (size_t)b * TT * TT;

    for (int ch = tid; ch < 1024; ch += 256) {
        int r = ch >> 4, cc = (ch & 15) * 4;
        float4 v = *(const float4*)(base + (size_t)(i0 + r) * 2304 + cc);
        float4 o;
        o.x = f2tf32f(v.x * 0.125f); o.y = f2tf32f(v.y * 0.125f);
        o.z = f2tf32f(v.z * 0.125f); o.w = f2tf32f(v.w * 0.125f);
        *(float4*)(sQ + r * SQ_LD + cc) = o;
    }

    float o[4][4];
    #pragma unroll
    for (int j = 0; j < 4; j++)
        #pragma unroll
        for (int e = 0; e < 4; e++) o[j][e] = 0.f;
    float m0r = -INFINITY, m1r = -INFINITY, l0 = 0.f, l1 = 0.f;

    int ntiles = (i0 == 0) ? (TT / 64) : (i0 >> 6) + 1;
    int rw0 = wm * 16 + g, rw1 = rw0 + 8;

    {
        const float* kb_ = base + 768;
        const float* vb_ = base + 1536;
        for (int ch = tid; ch < 1024; ch += 256) {
            int r = ch >> 4, cc = (ch & 15) * 4;
            CP_ASYNC16(sKu + (r * SQ_LD + cc) * 4, kb_ + (size_t)r * 2304 + cc);
            CP_ASYNC16(sVu + (r * SV_LD + cc) * 4, vb_ + (size_t)r * 2304 + cc);
        }
        CP_COMMIT();
    }

    for (int t = 0; t < ntiles; t++) {
        int j0 = t * 64, buf = t & 1;
        CP_WAIT0();
        __syncthreads();

        float c[4][4];
        #pragma unroll
        for (int j = 0; j < 4; j++)
            #pragma unroll
            for (int e = 0; e < 4; e++) c[j][e] = 0.f;
        const float* kS = sK + buf * 64 * SQ_LD;
        #pragma unroll
        for (int kb = 0; kb < 64; kb += 8) {
            uint32_t a[4], bfr[4][2];
            int qr = wm * 16;
            a[0] = __float_as_uint(sQ[(qr + g)     * SQ_LD + kb + tig]);
            a[1] = __float_as_uint(sQ[(qr + 8 + g) * SQ_LD + kb + tig]);
            a[2] = __float_as_uint(sQ[(qr + g)     * SQ_LD + kb + tig + 4]);
            a[3] = __float_as_uint(sQ[(qr + 8 + g) * SQ_LD + kb + tig + 4]);
            #pragma unroll
            for (int j = 0; j < 4; j++) {
                int r = wn * 32 + j * 8 + g;
                bfr[j][0] = __float_as_uint(kS[r * SQ_LD + kb + tig]);
                bfr[j][1] = __float_as_uint(kS[r * SQ_LD + kb + tig + 4]);
            }
            #pragma unroll
            for (int j = 0; j < 4; j++)
                MMA_TF32(c[j][0], c[j][1], c[j][2], c[j][3],
                         a[0], a[1], a[2], a[3], bfr[j][0], bfr[j][1]);
        }

        int gi0 = i0 + rw0, gi1 = i0 + rw1;
        #pragma unroll
        for (int j = 0; j < 4; j++) {
            int gj = j0 + wn * 32 + j * 8 + 2 * tig;
            float2 b0 = *(const float2*)(biasB + (size_t)gi0 * TT + gj);
            float2 b1 = *(const float2*)(biasB + (size_t)gi1 * TT + gj);
            c[j][0] += b0.x; c[j][1] += b0.y;
            c[j][2] += b1.x; c[j][3] += b1.y;
        }

        float mx0 = c[0][0], mx1 = c[0][2];
        #pragma unroll
        for (int j = 0; j < 4; j++) {
            mx0 = fmaxf(mx0, fmaxf(c[j][0], c[j][1]));
            mx1 = fmaxf(mx1, fmaxf(c[j][2], c[j][3]));
        }
        mx0 = fmaxf(mx0, __shfl_xor_sync(0xffffffffu, mx0, 1));
        mx0 = fmaxf(mx0, __shfl_xor_sync(0xffffffffu, mx0, 2));
        mx1 = fmaxf(mx1, __shfl_xor_sync(0xffffffffu, mx1, 1));
        mx1 = fmaxf(mx1, __shfl_xor_sync(0xffffffffu, mx1, 2));
        if (tig == 0) { sMax[wn * 64 + rw0] = mx0; sMax[wn * 64 + rw1] = mx1; }
        __syncthreads();
        float mxc0 = fmaxf(sMax[rw0], sMax[64 + rw0]);
        float mxc1 = fmaxf(sMax[rw1], sMax[64 + rw1]);

        float mn0 = fmaxf(m0r, mxc0), mn1 = fmaxf(m1r, mxc1);
        float al0 = __expf(m0r - mn0), al1 = __expf(m1r - mn1);

        float sum0 = 0.f, sum1 = 0.f;
        #pragma unroll
        for (int j = 0; j < 4; j++) {
            int cw = wn * 32 + j * 8 + 2 * tig;
            float p00 = __expf(c[j][0] - mn0), p01 = __expf(c[j][1] - mn0);
            float p10 = __expf(c[j][2] - mn1), p11 = __expf(c[j][3] - mn1);
            sum0 += p00 + p01; sum1 += p10 + p11;
            float2 q0; q0.x = p00; q0.y = p01;
            float2 q1; q1.x = p10; q1.y = p11;
            *(float2*)(sP + rw0 * SQ_LD + cw) = q0;
            *(float2*)(sP + rw1 * SQ_LD + cw) = q1;
        }
        sum0 += __shfl_xor_sync(0xffffffffu, sum0, 1);
        sum0 += __shfl_xor_sync(0xffffffffu, sum0, 2);
        sum1 += __shfl_xor_sync(0xffffffffu, sum1, 1);
        sum1 += __shfl_xor_sync(0xffffffffu, sum1, 2);
        if (tig == 0) { sSum[wn * 64 + rw0] = sum0; sSum[wn * 64 + rw1] = sum1; }
        __syncthreads();
        float sc0 = sSum[rw0] + sSum[64 + rw0];
        float sc1 = sSum[rw1] + sSum[64 + rw1];

        l0 = l0 * al0 + sc0;  l1 = l1 * al1 + sc1;
        m0r = mn0;  m1r = mn1;
        #pragma unroll
        for (int j = 0; j < 4; j++) {
            o[j][0] *= al0; o[j][1] *= al0;
            o[j][2] *= al1; o[j][3] *= al1;
        }

        if (t + 1 < ntiles) {
            int nj0 = (t + 1) * 64, nb = buf ^ 1;
            const float* kb_ = base + 768;
            const float* vb_ = base + 1536;
            for (int ch = tid; ch < 1024; ch += 256) {
                int r = ch >> 4, cc = (ch & 15) * 4;
                CP_ASYNC16(sKu + (nb * 64 * SQ_LD + r * SQ_LD + cc) * 4, kb_ + (size_t)(nj0 + r) * 2304 + cc);
                CP_ASYNC16(sVu + (nb * 64 * SV_LD + r * SV_LD + cc) * 4, vb_ + (size_t)(nj0 + r) * 2304 + cc);
            }
            CP_COMMIT();
        }

        const float* vS = sV + buf * 64 * SV_LD;
        #pragma unroll
        for (int kb = 0; kb < 64; kb += 8) {
            uint32_t a[4], bfr[4][2];
            int pr = wm * 16;
            a[0] = __float_as_uint(sP[(pr + g)     * SQ_LD + kb + tig]);
            a[1] = __float_as_uint(sP[(pr + 8 + g) * SQ_LD + kb + tig]);
            a[2] = __float_as_uint(sP[(pr + g)     * SQ_LD + kb + tig + 4]);
            a[3] = __float_as_uint(sP[(pr + 8 + g) * SQ_LD + kb + tig + 4]);
            #pragma unroll
            for (int j = 0; j < 4; j++) {
                int nc = wn * 32 + j * 8 + g;
                bfr[j][0] = __float_as_uint(vS[(kb + tig)     * SV_LD + nc]);
                bfr[j][1] = __float_as_uint(vS[(kb + tig + 4) * SV_LD + nc]);
            }
            #pragma unroll
            for (int j = 0; j < 4; j++)
                MMA_TF32(o[j][0], o[j][1], o[j][2], o[j][3],
                         a[0], a[1], a[2], a[3], bfr[j][0], bfr[j][1]);
        }
        __syncthreads();
    }

    float inv0 = 1.f / l0, inv1 = 1.f / l1;
    int gr0 = b * TT + i0 + wm * 16 + g, gr1 = gr0 + 8;
    #pragma unroll
    for (int j = 0; j < 4; j++) {
        int col = h * 64 + wn * 32 + j * 8 + 2 * tig;
        float2 o0, o1;
        o0.x = f2tf32f(o[j][0] * inv0); o0.y = f2tf32f(o[j][1] * inv0);
        o1.x = f2tf32f(o[j][2] * inv1); o1.y = f2tf32f(o[j][3] * inv1);
        *(float2*)(outA + (size_t)gr0 * DD + col) = o0;
        *(float2*)(outA + (size_t)gr1 * DD + col) = o1;
    }
}

// ---------------- launch ----------------
extern "C" void kernel_launch(void* const* d_in, const int* in_sizes, int n_in,
                              void* d_out, int out_size) {
    const float* x     = (const float*)d_in[0];
    const float* tmat  = (const float*)d_in[1];
    const int*   pm    = (const int*)d_in[2];
    const float* wq = (const float*)d_in[3],  *bq = (const float*)d_in[4];
    const float* wk = (const float*)d_in[5],  *bk = (const float*)d_in[6];
    const float* wv = (const float*)d_in[7],  *bv = (const float*)d_in[8];
    const float* wp = (const float*)d_in[9],  *bp = (const float*)d_in[10];
    const float* t1w = (const float*)d_in[11], *t1b = (const float*)d_in[12];
    const float* t2w = (const float*)d_in[13], *t2b = (const float*)d_in[14];
    const float* f1w = (const float*)d_in[15], *f1b = (const float*)d_in[16];
    const float* f2w = (const float*)d_in[17], *f2b = (const float*)d_in[18];
    const float* ln1g = (const float*)d_in[19], *ln1b = (const float*)d_in[20];
    const float* ln2g = (const float*)d_in[21], *ln2b = (const float*)d_in[22];
    float* out = (float*)d_out;

    float* sc = nullptr;
    cudaGetSymbolAddress((void**)&sc, g_scratch);
    float* gH    = sc + OF_H;
    float* gQKV  = sc + OF_QKV;
    float* gBQKV = sc + OF_BQKV;
    float* gA    = sc + OF_A;
    float* gX2   = sc + OF_X2;
    float* gF    = sc + OF_F;
    float* wcT   = sc + OF_WQT;
    float* wpT   = sc + OF_WPT;
    float* f1T   = sc + OF_F1T;
    float* f2T   = sc + OF_F2T;

    cudaFuncSetAttribute(gemm_mma<0>, cudaFuncAttributeMaxDynamicSharedMemorySize, GEMM_SMEM);
    cudaFuncSetAttribute(gemm_mma<1>, cudaFuncAttributeMaxDynamicSharedMemorySize, GEMM_SMEM);
    cudaFuncSetAttribute(gemm_mma<2>, cudaFuncAttributeMaxDynamicSharedMemorySize, GEMM_SMEM);
    cudaFuncSetAttribute(flash_kernel, cudaFuncAttributeMaxDynamicSharedMemorySize, FS_TOT);

    dim3 tb(32, 8);
    transpose_attn<<<dim3(24, 24, 4), tb>>>(wq, wk, wv, wp, wcT);
    transpose_ffn<<<dim3(96, 24, 2), tb>>>(f1w, f1T, f2w, f2T);
    concat_bias<<<9, 256>>>(bq, bk, bv, gBQKV);
    bias_kernel<<<(BB * TT * TT) / 256, 256>>>(tmat, pm, t1w, t1b, t2w, t2b);
    ln_kernel<<<MROWS, 256>>>(x, ln1g, ln1b, gH);

    gemm_mma<0><<<dim3(2304 / BN, MROWS / BM), 256, GEMM_SMEM>>>(gH, wcT, gBQKV, nullptr, gQKV, 2304, DD);

    flash_kernel<<<dim3(TT / 64, BB * HH), 256, FS_TOT>>>(gQKV, gA);

    gemm_mma<1><<<dim3(DD / BN, MROWS / BM), 256, GEMM_SMEM>>>(gA, wpT, bp, x, gX2, DD, DD);

    ln_kernel<<<MROWS, 256>>>(gX2, ln2g, ln2b, gH);
    gemm_mma<2><<<dim3(FFC / BN, MROWS / BM), 256, GEMM_SMEM>>>(gH, f1T, f1b, nullptr, gF, FFC, DD);
    gemm_mma<1><<<dim3(DD / BN, MROWS / BM), 256, GEMM_SMEM>>>(gF, f2T, f2b, gX2, out, DD, FFC);
}

// round 8
// speedup vs baseline: 3.0401x; 1.0948x over previous
#include <cuda_runtime.h>
#include <math.h>
#include <stdint.h>

// ---------------- problem constants ----------------
#define BB 4
#define TT 512
#define DD 768
#define HH 12
#define DKC 64
#define FFC 3072
#define TBN 64
#define NEGV (-1e9f)
#define E_CONST 2.718281828459045f
#define MROWS (BB*TT)            // 2048

// ---------------- scratch layout (floats) ----------------
#define OF_H    0ull
#define OF_BIAS 6291456ull
#define OF_S    7340032ull
#define OF_QKV  OF_S
#define OF_BQKV (OF_S + 4718592ull)
#define OF_A    19922944ull
#define OF_X2   21495808ull
#define OF_F    23068672ull
#define OF_WQT  29360128ull
#define OF_WPT  31129600ull
#define OF_F1T  31719424ull
#define OF_F2T  34078720ull
#define SCRATCH_TOTAL 36438016ull

__device__ float g_scratch[SCRATCH_TOTAL];

// ---------------- helpers ----------------
__device__ __forceinline__ uint32_t smem_u32(const void* p) {
    uint32_t a;
    asm("{ .reg .u64 t; cvta.to.shared.u64 t, %1; cvt.u32.u64 %0, t; }" : "=r"(a) : "l"(p));
    return a;
}
__device__ __forceinline__ float f2tf32f(float f) {
    uint32_t r; asm("cvt.rna.tf32.f32 %0, %1;" : "=r"(r) : "f"(f));
    return __uint_as_float(r);
}
#define CP_ASYNC16(dst_u32, src_ptr) \
    asm volatile("cp.async.cg.shared.global [%0], [%1], 16;\n" :: "r"(dst_u32), "l"(__cvta_generic_to_global(src_ptr)))
#define CP_COMMIT() asm volatile("cp.async.commit_group;\n" ::: "memory")
#define CP_WAIT2()  asm volatile("cp.async.wait_group 2;\n" ::: "memory")
#define CP_WAIT1()  asm volatile("cp.async.wait_group 1;\n" ::: "memory")
#define CP_WAIT0()  asm volatile("cp.async.wait_group 0;\n" ::: "memory")

#define MMA_TF32(c0,c1,c2,c3,a0,a1,a2,a3,b0,b1) \
    asm volatile("mma.sync.aligned.m16n8k8.row.col.f32.tf32.tf32.f32 " \
                 "{%0,%1,%2,%3}, {%4,%5,%6,%7}, {%8,%9}, {%0,%1,%2,%3};\n" \
                 : "+f"(c0), "+f"(c1), "+f"(c2), "+f"(c3) \
                 : "r"(a0), "r"(a1), "r"(a2), "r"(a3), "r"(b0), "r"(b1))

#define LDSM_X4(d0,d1,d2,d3,addr) \
    asm volatile("ldmatrix.sync.aligned.m8n8.x4.shared.b16 {%0,%1,%2,%3}, [%4];\n" \
                 : "=r"(d0), "=r"(d1), "=r"(d2), "=r"(d3) : "r"(addr))

#define LDT 20

// =======================================================================
// small-tile GEMM — 128x64, 4-stage (validated R7). For N=768 GEMMs.
// =======================================================================
#define BM 128
#define BN 64
#define GSTAGES 4
#define GEMM_SMEM ((GSTAGES*(BM+BN)*LDT)*4)   // 61440

template <int EPI>
__global__ __launch_bounds__(256, 2) void gemm_mma(const float* __restrict__ A,
                                                   const float* __restrict__ Wt,
                                                   const float* __restrict__ bias,
                                                   const float* __restrict__ res,
                                                   float* __restrict__ C,
                                                   int N, int K) {
    extern __shared__ float dsm[];
    float* AsBase = dsm;
    float* BsBase = dsm + GSTAGES * BM * LDT;

    int tid = threadIdx.x;
    int warp = tid >> 5, lane = tid & 31;
    int wm = warp >> 1, wn = warp & 1;
    int g = lane >> 2, tig = lane & 3;
    int m0 = blockIdx.y * BM, n0 = blockIdx.x * BN;

    int ar0 = tid >> 2,            ac0 = (tid & 3) * 4;
    int ar1 = (tid + 256) >> 2,    ac1 = ((tid + 256) & 3) * 4;
    int br  = tid >> 2,            bc  = (tid & 3) * 4;

    uint32_t sA = smem_u32(AsBase);
    uint32_t sB = smem_u32(BsBase);
    const uint32_t bufA = BM * LDT * 4, bufB = BN * LDT * 4;

    int q = lane >> 3, l7 = lane & 7;
    int a_row = wm * 32 + (q & 1) * 8 + l7,  a_col = (q >> 1) * 4;
    int b_row = wn * 32 + (q >> 1) * 8 + l7, b_col = (q & 1) * 4;
    uint32_t aAddr0 = sA + (uint32_t)(a_row * LDT + a_col) * 4;
    uint32_t bAddr0 = sB + (uint32_t)(b_row * LDT + b_col) * 4;

    const int nk = K >> 4;

    #pragma unroll
    for (int pf = 0; pf < 3; pf++) {
        int k0 = pf * 16;
        CP_ASYNC16(sA + pf * bufA + (ar0 * LDT + ac0) * 4, A + (size_t)(m0 + ar0) * K + k0 + ac0);
        CP_ASYNC16(sA + pf * bufA + (ar1 * LDT + ac1) * 4, A + (size_t)(m0 + ar1) * K + k0 + ac1);
        CP_ASYNC16(sB + pf * bufB + (br * LDT + bc) * 4,  Wt + (size_t)(n0 + br) * K + k0 + bc);
        CP_COMMIT();
    }

    float c[2][4][4];
    #pragma unroll
    for (int i = 0; i < 2; i++)
        #pragma unroll
        for (int j = 0; j < 4; j++)
            #pragma unroll
            for (int e = 0; e < 4; e++) c[i][j][e] = 0.f;

    for (int kt = 0; kt < nk; kt++) {
        int buf = kt & (GSTAGES - 1);
        CP_WAIT2();
        __syncthreads();

        uint32_t aBuf = aAddr0 + buf * bufA;
        uint32_t bBuf = bAddr0 + buf * bufB;
        #pragma unroll
        for (int ks = 0; ks < 2; ks++) {
            uint32_t kOff = (uint32_t)(ks * 8) * 4;
            uint32_t a[2][4], b[4][2];
            #pragma unroll
            for (int i = 0; i < 2; i++)
                LDSM_X4(a[i][0], a[i][1], a[i][2], a[i][3],
                        aBuf + (uint32_t)(i * 16 * LDT) * 4 + kOff);
            #pragma unroll
            for (int p = 0; p < 2; p++)
                LDSM_X4(b[2*p][0], b[2*p][1], b[2*p+1][0], b[2*p+1][1],
                        bBuf + (uint32_t)(p * 16 * LDT) * 4 + kOff);
            #pragma unroll
            for (int i = 0; i < 2; i++)
                #pragma unroll
                for (int j = 0; j < 4; j++)
                    MMA_TF32(c[i][j][0], c[i][j][1], c[i][j][2], c[i][j][3],
                             a[i][0], a[i][1], a[i][2], a[i][3], b[j][0], b[j][1]);
        }

        if (kt + 3 < nk) {
            int k0 = (kt + 3) * 16;
            int nbuf = (kt + 3) & (GSTAGES - 1);
            CP_ASYNC16(sA + nbuf * bufA + (ar0 * LDT + ac0) * 4, A + (size_t)(m0 + ar0) * K + k0 + ac0);
            CP_ASYNC16(sA + nbuf * bufA + (ar1 * LDT + ac1) * 4, A + (size_t)(m0 + ar1) * K + k0 + ac1);
            CP_ASYNC16(sB + nbuf * bufB + (br * LDT + bc) * 4,  Wt + (size_t)(n0 + br) * K + k0 + bc);
        }
        CP_COMMIT();
    }

    #pragma unroll
    for (int i = 0; i < 2; i++) {
        int row0 = m0 + wm * 32 + i * 16 + g;
        #pragma unroll
        for (int j = 0; j < 4; j++) {
            int col = n0 + wn * 32 + j * 8 + 2 * tig;
            float b0 = bias[col], b1 = bias[col + 1];
            #pragma unroll
            for (int half = 0; half < 2; half++) {
                int r = row0 + half * 8;
                float v0 = c[i][j][half * 2 + 0] + b0;
                float v1 = c[i][j][half * 2 + 1] + b1;
                if (EPI == 1) {
                    float2 r2 = *(const float2*)(res + (size_t)r * N + col);
                    v0 += r2.x; v1 += r2.y;
                }
                if (EPI == 2) {
                    v0 = 0.5f * v0 * (1.f + erff(v0 * 0.70710678118654752f));
                    v1 = 0.5f * v1 * (1.f + erff(v1 * 0.70710678118654752f));
                    v0 = f2tf32f(v0); v1 = f2tf32f(v1);
                }
                float2 o; o.x = v0; o.y = v1;
                *(float2*)(C + (size_t)r * N + col) = o;
            }
        }
    }
}

// =======================================================================
// big-tile GEMM — 128x128, 3-stage, warp tile 32x64. For N>=2304 GEMMs.
// =======================================================================
#define BM2 128
#define BN2 128
#define GST2 3
#define GEMM_SMEM2 ((GST2*(BM2+BN2)*LDT)*4)   // 61440

template <int EPI>  // 0 bias, 2 bias+gelu(+tf32)
__global__ __launch_bounds__(256, 2) void gemm_big(const float* __restrict__ A,
                                                   const float* __restrict__ Wt,
                                                   const float* __restrict__ bias,
                                                   float* __restrict__ C,
                                                   int N, int K) {
    extern __shared__ float dsm[];
    float* AsBase = dsm;
    float* BsBase = dsm + GST2 * BM2 * LDT;

    int tid = threadIdx.x;
    int warp = tid >> 5, lane = tid & 31;
    int wm = warp >> 1, wn = warp & 1;
    int g = lane >> 2, tig = lane & 3;
    int m0 = blockIdx.y * BM2, n0 = blockIdx.x * BN2;

    int r0 = tid >> 2,            c0_ = (tid & 3) * 4;
    int r1 = (tid + 256) >> 2,    c1_ = ((tid + 256) & 3) * 4;

    uint32_t sA = smem_u32(AsBase);
    uint32_t sB = smem_u32(BsBase);
    const uint32_t bufA = BM2 * LDT * 4, bufB = BN2 * LDT * 4;

    int q = lane >> 3, l7 = lane & 7;
    int a_row = wm * 32 + (q & 1) * 8 + l7,  a_col = (q >> 1) * 4;
    int b_row = wn * 64 + (q >> 1) * 8 + l7, b_col = (q & 1) * 4;
    uint32_t aAddr0 = sA + (uint32_t)(a_row * LDT + a_col) * 4;
    uint32_t bAddr0 = sB + (uint32_t)(b_row * LDT + b_col) * 4;

    const int nk = K >> 4;

    #pragma unroll
    for (int pf = 0; pf < 2; pf++) {
        int k0 = pf * 16;
        CP_ASYNC16(sA + pf * bufA + (r0 * LDT + c0_) * 4, A + (size_t)(m0 + r0) * K + k0 + c0_);
        CP_ASYNC16(sA + pf * bufA + (r1 * LDT + c1_) * 4, A + (size_t)(m0 + r1) * K + k0 + c1_);
        CP_ASYNC16(sB + pf * bufB + (r0 * LDT + c0_) * 4, Wt + (size_t)(n0 + r0) * K + k0 + c0_);
        CP_ASYNC16(sB + pf * bufB + (r1 * LDT + c1_) * 4, Wt + (size_t)(n0 + r1) * K + k0 + c1_);
        CP_COMMIT();
    }

    float c[2][8][4];
    #pragma unroll
    for (int i = 0; i < 2; i++)
        #pragma unroll
        for (int j = 0; j < 8; j++)
            #pragma unroll
            for (int e = 0; e < 4; e++) c[i][j][e] = 0.f;

    for (int kt = 0; kt < nk; kt++) {
        int buf = kt % GST2;
        CP_WAIT1();
        __syncthreads();

        uint32_t aBuf = aAddr0 + buf * bufA;
        uint32_t bBuf = bAddr0 + buf * bufB;
        #pragma unroll
        for (int ks = 0; ks < 2; ks++) {
            uint32_t kOff = (uint32_t)(ks * 8) * 4;
            uint32_t a[2][4], b[8][2];
            #pragma unroll
            for (int i = 0; i < 2; i++)
                LDSM_X4(a[i][0], a[i][1], a[i][2], a[i][3],
                        aBuf + (uint32_t)(i * 16 * LDT) * 4 + kOff);
            #pragma unroll
            for (int p = 0; p < 4; p++)
                LDSM_X4(b[2*p][0], b[2*p][1], b[2*p+1][0], b[2*p+1][1],
                        bBuf + (uint32_t)(p * 16 * LDT) * 4 + kOff);
            #pragma unroll
            for (int i = 0; i < 2; i++)
                #pragma unroll
                for (int j = 0; j < 8; j++)
                    MMA_TF32(c[i][j][0], c[i][j][1], c[i][j][2], c[i][j][3],
                             a[i][0], a[i][1], a[i][2], a[i][3], b[j][0], b[j][1]);
        }

        if (kt + 2 < nk) {
            int k0 = (kt + 2) * 16;
            int nbuf = (kt + 2) % GST2;
            CP_ASYNC16(sA + nbuf * bufA + (r0 * LDT + c0_) * 4, A + (size_t)(m0 + r0) * K + k0 + c0_);
            CP_ASYNC16(sA + nbuf * bufA + (r1 * LDT + c1_) * 4, A + (size_t)(m0 + r1) * K + k0 + c1_);
            CP_ASYNC16(sB + nbuf * bufB + (r0 * LDT + c0_) * 4, Wt + (size_t)(n0 + r0) * K + k0 + c0_);
            CP_ASYNC16(sB + nbuf * bufB + (r1 * LDT + c1_) * 4, Wt + (size_t)(n0 + r1) * K + k0 + c1_);
        }
        CP_COMMIT();
    }

    #pragma unroll
    for (int i = 0; i < 2; i++) {
        int row0 = m0 + wm * 32 + i * 16 + g;
        #pragma unroll
        for (int j = 0; j < 8; j++) {
            int col = n0 + wn * 64 + j * 8 + 2 * tig;
            float b0 = bias[col], b1 = bias[col + 1];
            #pragma unroll
            for (int half = 0; half < 2; half++) {
                int r = row0 + half * 8;
                float v0 = c[i][j][half * 2 + 0] + b0;
                float v1 = c[i][j][half * 2 + 1] + b1;
                if (EPI == 2) {
                    v0 = 0.5f * v0 * (1.f + erff(v0 * 0.70710678118654752f));
                    v1 = 0.5f * v1 * (1.f + erff(v1 * 0.70710678118654752f));
                    v0 = f2tf32f(v0); v1 = f2tf32f(v1);
                }
                float2 o; o.x = v0; o.y = v1;
                *(float2*)(C + (size_t)r * N + col) = o;
            }
        }
    }
}

// ---------------- merged transposes (tf32-rounded) ----------------
__global__ __launch_bounds__(256) void transpose_attn(const float* __restrict__ wq,
                                                      const float* __restrict__ wk,
                                                      const float* __restrict__ wv,
                                                      const float* __restrict__ wp,
                                                      float* __restrict__ dst) {
    __shared__ float t[32][33];
    int z = blockIdx.z;
    const float* W = (z == 0) ? wq : (z == 1) ? wk : (z == 2) ? wv : wp;
    float* Wt = dst + (size_t)z * 589824;
    int n0 = blockIdx.x * 32, k0 = blockIdx.y * 32;
    int tx = threadIdx.x, ty = threadIdx.y;
    #pragma unroll
    for (int i = 0; i < 32; i += 8)
        t[ty + i][tx] = W[(size_t)(k0 + ty + i) * DD + n0 + tx];
    __syncthreads();
    #pragma unroll
    for (int i = 0; i < 32; i += 8)
        Wt[(size_t)(n0 + ty + i) * DD + k0 + tx] = f2tf32f(t[tx][ty + i]);
}

__global__ __launch_bounds__(256) void transpose_ffn(const float* __restrict__ f1w,
                                                     float* __restrict__ f1T,
                                                     const float* __restrict__ f2w,
                                                     float* __restrict__ f2T) {
    __shared__ float t[32][33];
    int z = blockIdx.z;
    const float* W; float* Wt; int K, N, n0, k0;
    if (z == 0) { W = f1w; Wt = f1T; K = DD;  N = FFC; n0 = blockIdx.x * 32; k0 = blockIdx.y * 32; }
    else        { W = f2w; Wt = f2T; K = FFC; N = DD;  n0 = blockIdx.y * 32; k0 = blockIdx.x * 32; }
    int tx = threadIdx.x, ty = threadIdx.y;
    #pragma unroll
    for (int i = 0; i < 32; i += 8)
        t[ty + i][tx] = W[(size_t)(k0 + ty + i) * N + n0 + tx];
    __syncthreads();
    #pragma unroll
    for (int i = 0; i < 32; i += 8)
        Wt[(size_t)(n0 + ty + i) * K + k0 + tx] = f2tf32f(t[tx][ty + i]);
}

__global__ void concat_bias(const float* __restrict__ a, const float* __restrict__ b,
                            const float* __restrict__ c, float* __restrict__ o) {
    int t = blockIdx.x * 256 + threadIdx.x;
    if (t < 768) o[t] = a[t];
    else if (t < 1536) o[t] = b[t - 768];
    else if (t < 2304) o[t] = c[t - 1536];
}

// ---------------- LayerNorm (tf32-rounded output) ----------------
__global__ __launch_bounds__(256) void ln_kernel(const float* __restrict__ x,
                                                 const float* __restrict__ g,
                                                 const float* __restrict__ b,
                                                 float* __restrict__ out) {
    int row = blockIdx.x;
    const float* xr = x + (size_t)row * DD;
    float s = 0.f, s2 = 0.f;
    for (int i = threadIdx.x; i < DD; i += 256) { float v = xr[i]; s += v; s2 += v * v; }
    #pragma unroll
    for (int o = 16; o > 0; o >>= 1) {
        s  += __shfl_xor_sync(0xffffffffu, s,  o);
        s2 += __shfl_xor_sync(0xffffffffu, s2, o);
    }
    __shared__ float ws[8], ws2[8];
    int w = threadIdx.x >> 5, l = threadIdx.x & 31;
    if (l == 0) { ws[w] = s; ws2[w] = s2; }
    __syncthreads();
    if (w == 0) {
        s  = (l < 8) ? ws[l]  : 0.f;
        s2 = (l < 8) ? ws2[l] : 0.f;
        #pragma unroll
        for (int o = 4; o > 0; o >>= 1) {
            s  += __shfl_xor_sync(0xffffffffu, s,  o);
            s2 += __shfl_xor_sync(0xffffffffu, s2, o);
        }
        if (l == 0) { ws[0] = s; ws2[0] = s2; }
    }
    __syncthreads();
    float mean = ws[0] * (1.f / DD);
    float var  = ws2[0] * (1.f / DD) - mean * mean;
    float inv  = rsqrtf(var + 1e-5f);
    float* orow = out + (size_t)row * DD;
    for (int i = threadIdx.x; i < DD; i += 256)
        orow[i] = f2tf32f((xr[i] - mean) * inv * g[i] + b[i]);
}

// ---------------- temporal bias w/ masks baked in (fast math) ----------------
__global__ __launch_bounds__(256) void bias_kernel(const float* __restrict__ tm,
                                                   const int* __restrict__ pm,
                                                   const float* __restrict__ t1w,
                                                   const float* __restrict__ t1b,
                                                   const float* __restrict__ t2w,
                                                   const float* __restrict__ t2b) {
    __shared__ float w1[TBN], b1[TBN], w2[TBN];
    int t = threadIdx.x;
    if (t < TBN) { w1[t] = t1w[t]; b1[t] = t1b[t]; w2[t] = t2w[t]; }
    __syncthreads();
    size_t idx = (size_t)blockIdx.x * 256 + t;
    int rem = (int)(idx % (TT * TT));
    int i = rem / TT, j = rem % TT;
    float u = __fdividef(1.f, __logf(E_CONST + tm[idx]));
    float s = t2b[0];
    #pragma unroll
    for (int k = 0; k < TBN; k++) {
        float z = fmaf(u, w1[k], b1[k]);
        z = (z > 0.f) ? z : 0.2f * z;
        s = fmaf(z, w2[k], s);
    }
    bool masked = (pm[idx] == 0) || (j > i && i > 0);
    g_scratch[OF_BIAS + idx] = masked ? NEGV : s;
}

// =======================================================================
// flash attention (validated R5) — unchanged
// =======================================================================
#define SQ_LD 68
#define SV_LD 72
#define FS_Q    0
#define FS_K    (64*68)
#define FS_V    (FS_K + 2*64*68)
#define FS_P    (FS_V + 2*64*72)
#define FS_STAT (FS_P + 64*68)
#define FS_TOT  ((FS_STAT + 256) * 4)

__global__ __launch_bounds__(256, 2) void flash_kernel(const float* __restrict__ qkv,
                                                       float* __restrict__ outA) {
    extern __shared__ float fs[];
    float* sQ = fs + FS_Q;
    float* sK = fs + FS_K;
    float* sV = fs + FS_V;
    float* sP = fs + FS_P;
    float* sMax = fs + FS_STAT;
    float* sSum = fs + FS_STAT + 128;
    uint32_t sKu = smem_u32(sK), sVu = smem_u32(sV);

    int tid = threadIdx.x;
    int warp = tid >> 5, lane = tid & 31;
    int wm = warp >> 1, wn = warp & 1;
    int g = lane >> 2, tig = lane & 3;
    int i0 = blockIdx.x * 64;
    int bh = blockIdx.y, b = bh / HH, h = bh % HH;

    const float* base = qkv + (size_t)b * TT * 2304 + h * 64;
    const float* biasB = g_scratch + OF_BIAS + (size_t)b * TT * TT;

    for (int ch = tid; ch < 1024; ch += 256) {
        int r = ch >> 4, cc = (ch & 15) * 4;
        float4 v = *(const float4*)(base + (size_t)(i0 + r) * 2304 + cc);
        float4 o;
        o.x = f2tf32f(v.x * 0.125f); o.y = f2tf32f(v.y * 0.125f);
        o.z = f2tf32f(v.z * 0.125f); o.w = f2tf32f(v.w * 0.125f);
        *(float4*)(sQ + r * SQ_LD + cc) = o;
    }

    float o[4][4];
    #pragma unroll
    for (int j = 0; j < 4; j++)
        #pragma unroll
        for (int e = 0; e < 4; e++) o[j][e] = 0.f;
    float m0r = -INFINITY, m1r = -INFINITY, l0 = 0.f, l1 = 0.f;

    int ntiles = (i0 == 0) ? (TT / 64) : (i0 >> 6) + 1;
    int rw0 = wm * 16 + g, rw1 = rw0 + 8;

    {
        const float* kb_ = base + 768;
        const float* vb_ = base + 1536;
        for (int ch = tid; ch < 1024; ch += 256) {
            int r = ch >> 4, cc = (ch & 15) * 4;
            CP_ASYNC16(sKu + (r * SQ_LD + cc) * 4, kb_ + (size_t)r * 2304 + cc);
            CP_ASYNC16(sVu + (r * SV_LD + cc) * 4, vb_ + (size_t)r * 2304 + cc);
        }
        CP_COMMIT();
    }

    for (int t = 0; t < ntiles; t++) {
        int j0 = t * 64, buf = t & 1;
        CP_WAIT0();
        __syncthreads();

        float c[4][4];
        #pragma unroll
        for (int j = 0; j < 4; j++)
            #pragma unroll
            for (int e = 0; e < 4; e++) c[j][e] = 0.f;
        const float* kS = sK + buf * 64 * SQ_LD;
        #pragma unroll
        for (int kb = 0; kb < 64; kb += 8) {
            uint32_t a[4], bfr[4][2];
            int qr = wm * 16;
            a[0] = __float_as_uint(sQ[(qr + g)     * SQ_LD + kb + tig]);
            a[1] = __float_as_uint(sQ[(qr + 8 + g) * SQ_LD + kb + tig]);
            a[2] = __float_as_uint(sQ[(qr + g)     * SQ_LD + kb + tig + 4]);
            a[3] = __float_as_uint(sQ[(qr + 8 + g) * SQ_LD + kb + tig + 4]);
            #pragma unroll
            for (int j = 0; j < 4; j++) {
                int r = wn * 32 + j * 8 + g;
                bfr[j][0] = __float_as_uint(kS[r * SQ_LD + kb + tig]);
                bfr[j][1] = __float_as_uint(kS[r * SQ_LD + kb + tig + 4]);
            }
            #pragma unroll
            for (int j = 0; j < 4; j++)
                MMA_TF32(c[j][0], c[j][1], c[j][2], c[j][3],
                         a[0], a[1], a[2], a[3], bfr[j][0], bfr[j][1]);
        }

        int gi0 = i0 + rw0, gi1 = i0 + rw1;
        #pragma unroll
        for (int j = 0; j < 4; j++) {
            int gj = j0 + wn * 32 + j * 8 + 2 * tig;
            float2 b0 = *(const float2*)(biasB + (size_t)gi0 * TT + gj);
            float2 b1 = *(const float2*)(biasB + (size_t)gi1 * TT + gj);
            c[j][0] += b0.x; c[j][1] += b0.y;
            c[j][2] += b1.x; c[j][3] += b1.y;
        }

        float mx0 = c[0][0], mx1 = c[0][2];
        #pragma unroll
        for (int j = 0; j < 4; j++) {
            mx0 = fmaxf(mx0, fmaxf(c[j][0], c[j][1]));
            mx1 = fmaxf(mx1, fmaxf(c[j][2], c[j][3]));
        }
        mx0 = fmaxf(mx0, __shfl_xor_sync(0xffffffffu, mx0, 1));
        mx0 = fmaxf(mx0, __shfl_xor_sync(0xffffffffu, mx0, 2));
        mx1 = fmaxf(mx1, __shfl_xor_sync(0xffffffffu, mx1, 1));
        mx1 = fmaxf(mx1, __shfl_xor_sync(0xffffffffu, mx1, 2));
        if (tig == 0) { sMax[wn * 64 + rw0] = mx0; sMax[wn * 64 + rw1] = mx1; }
        __syncthreads();
        float mxc0 = fmaxf(sMax[rw0], sMax[64 + rw0]);
        float mxc1 = fmaxf(sMax[rw1], sMax[64 + rw1]);

        float mn0 = fmaxf(m0r, mxc0), mn1 = fmaxf(m1r, mxc1);
        float al0 = __expf(m0r - mn0), al1 = __expf(m1r - mn1);

        float sum0 = 0.f, sum1 = 0.f;
        #pragma unroll
        for (int j = 0; j < 4; j++) {
            int cw = wn * 32 + j * 8 + 2 * tig;
            float p00 = __expf(c[j][0] - mn0), p01 = __expf(c[j][1] - mn0);
            float p10 = __expf(c[j][2] - mn1), p11 = __expf(c[j][3] - mn1);
            sum0 += p00 + p01; sum1 += p10 + p11;
            float2 q0; q0.x = p00; q0.y = p01;
            float2 q1; q1.x = p10; q1.y = p11;
            *(float2*)(sP + rw0 * SQ_LD + cw) = q0;
            *(float2*)(sP + rw1 * SQ_LD + cw) = q1;
        }
        sum0 += __shfl_xor_sync(0xffffffffu, sum0, 1);
        sum0 += __shfl_xor_sync(0xffffffffu, sum0, 2);
        sum1 += __shfl_xor_sync(0xffffffffu, sum1, 1);
        sum1 += __shfl_xor_sync(0xffffffffu, sum1, 2);
        if (tig == 0) { sSum[wn * 64 + rw0] = sum0; sSum[wn * 64 + rw1] = sum1; }
        __syncthreads();
        float sc0 = sSum[rw0] + sSum[64 + rw0];
        float sc1 = sSum[rw1] + sSum[64 + rw1];

        l0 = l0 * al0 + sc0;  l1 = l1 * al1 + sc1;
        m0r = mn0;  m1r = mn1;
        #pragma unroll
        for (int j = 0; j < 4; j++) {
            o[j][0] *= al0; o[j][1] *= al0;
            o[j][2] *= al1; o[j][3] *= al1;
        }

        if (t + 1 < ntiles) {
            int nj0 = (t + 1) * 64, nb = buf ^ 1;
            const float* kb_ = base + 768;
            const float* vb_ = base + 1536;
            for (int ch = tid; ch < 1024; ch += 256) {
                int r = ch >> 4, cc = (ch & 15) * 4;
                CP_ASYNC16(sKu + (nb * 64 * SQ_LD + r * SQ_LD + cc) * 4, kb_ + (size_t)(nj0 + r) * 2304 + cc);
                CP_ASYNC16(sVu + (nb * 64 * SV_LD + r * SV_LD + cc) * 4, vb_ + (size_t)(nj0 + r) * 2304 + cc);
            }
            CP_COMMIT();
        }

        const float* vS = sV + buf * 64 * SV_LD;
        #pragma unroll
        for (int kb = 0; kb < 64; kb += 8) {
            uint32_t a[4], bfr[4][2];
            int pr = wm * 16;
            a[0] = __float_as_uint(sP[(pr + g)     * SQ_LD + kb + tig]);
            a[1] = __float_as_uint(sP[(pr + 8 + g) * SQ_LD + kb + tig]);
            a[2] = __float_as_uint(sP[(pr + g)     * SQ_LD + kb + tig + 4]);
            a[3] = __float_as_uint(sP[(pr + 8 + g) * SQ_LD + kb + tig + 4]);
            #pragma unroll
            for (int j = 0; j < 4; j++) {
                int nc = wn * 32 + j * 8 + g;
                bfr[j][0] = __float_as_uint(vS[(kb + tig)     * SV_LD + nc]);
                bfr[j][1] = __float_as_uint(vS[(kb + tig + 4) * SV_LD + nc]);
            }
            #pragma unroll
            for (int j = 0; j < 4; j++)
                MMA_TF32(o[j][0], o[j][1], o[j][2], o[j][3],
                         a[0], a[1], a[2], a[3], bfr[j][0], bfr[j][1]);
        }
        __syncthreads();
    }

    float inv0 = 1.f / l0, inv1 = 1.f / l1;
    int gr0 = b * TT + i0 + wm * 16 + g, gr1 = gr0 + 8;
    #pragma unroll
    for (int j = 0; j < 4; j++) {
        int col = h * 64 + wn * 32 + j * 8 + 2 * tig;
        float2 o0, o1;
        o0.x = f2tf32f(o[j][0] * inv0); o0.y = f2tf32f(o[j][1] * inv0);
        o1.x = f2tf32f(o[j][2] * inv1); o1.y = f2tf32f(o[j][3] * inv1);
        *(float2*)(outA + (size_t)gr0 * DD + col) = o0;
        *(float2*)(outA + (size_t)gr1 * DD + col) = o1;
    }
}

// ---------------- launch ----------------
extern "C" void kernel_launch(void* const* d_in, const int* in_sizes, int n_in,
                              void* d_out, int out_size) {
    const float* x     = (const float*)d_in[0];
    const float* tmat  = (const float*)d_in[1];
    const int*   pm    = (const int*)d_in[2];
    const float* wq = (const float*)d_in[3],  *bq = (const float*)d_in[4];
    const float* wk = (const float*)d_in[5],  *bk = (const float*)d_in[6];
    const float* wv = (const float*)d_in[7],  *bv = (const float*)d_in[8];
    const float* wp = (const float*)d_in[9],  *bp = (const float*)d_in[10];
    const float* t1w = (const float*)d_in[11], *t1b = (const float*)d_in[12];
    const float* t2w = (const float*)d_in[13], *t2b = (const float*)d_in[14];
    const float* f1w = (const float*)d_in[15], *f1b = (const float*)d_in[16];
    const float* f2w = (const float*)d_in[17], *f2b = (const float*)d_in[18];
    const float* ln1g = (const float*)d_in[19], *ln1b = (const float*)d_in[20];
    const float* ln2g = (const float*)d_in[21], *ln2b = (const float*)d_in[22];
    float* out = (float*)d_out;

    float* sc = nullptr;
    cudaGetSymbolAddress((void**)&sc, g_scratch);
    float* gH    = sc + OF_H;
    float* gQKV  = sc + OF_QKV;
    float* gBQKV = sc + OF_BQKV;
    float* gA    = sc + OF_A;
    float* gX2   = sc + OF_X2;
    float* gF    = sc + OF_F;
    float* wcT   = sc + OF_WQT;
    float* wpT   = sc + OF_WPT;
    float* f1T   = sc + OF_F1T;
    float* f2T   = sc + OF_F2T;

    cudaFuncSetAttribute(gemm_mma<1>, cudaFuncAttributeMaxDynamicSharedMemorySize, GEMM_SMEM);
    cudaFuncSetAttribute(gemm_big<0>, cudaFuncAttributeMaxDynamicSharedMemorySize, GEMM_SMEM2);
    cudaFuncSetAttribute(gemm_big<2>, cudaFuncAttributeMaxDynamicSharedMemorySize, GEMM_SMEM2);
    cudaFuncSetAttribute(flash_kernel, cudaFuncAttributeMaxDynamicSharedMemorySize, FS_TOT);

    dim3 tb(32, 8);
    transpose_attn<<<dim3(24, 24, 4), tb>>>(wq, wk, wv, wp, wcT);
    transpose_ffn<<<dim3(96, 24, 2), tb>>>(f1w, f1T, f2w, f2T);
    concat_bias<<<9, 256>>>(bq, bk, bv, gBQKV);
    bias_kernel<<<(BB * TT * TT) / 256, 256>>>(tmat, pm, t1w, t1b, t2w, t2b);
    ln_kernel<<<MROWS, 256>>>(x, ln1g, ln1b, gH);

    gemm_big<0><<<dim3(2304 / BN2, MROWS / BM2), 256, GEMM_SMEM2>>>(gH, wcT, gBQKV, gQKV, 2304, DD);

    flash_kernel<<<dim3(TT / 64, BB * HH), 256, FS_TOT>>>(gQKV, gA);

    gemm_mma<1><<<dim3(DD / BN, MROWS / BM), 256, GEMM_SMEM>>>(gA, wpT, bp, x, gX2, DD, DD);

    ln_kernel<<<MROWS, 256>>>(gX2, ln2g, ln2b, gH);
    gemm_big<2><<<dim3(FFC / BN2, MROWS / BM2), 256, GEMM_SMEM2>>>(gH, f1T, f1b, gF, FFC, DD);
    gemm_mma<1><<<dim3(DD / BN, MROWS / BM), 256, GEMM_SMEM>>>(gF, f2T, f2b, gX2, out, DD, FFC);
}

// round 9
// speedup vs baseline: 3.2009x; 1.0529x over previous
#include <cuda_runtime.h>
#include <math.h>
#include <stdint.h>

// ---------------- problem constants ----------------
#define BB 4
#define TT 512
#define DD 768
#define HH 12
#define DKC 64
#define FFC 3072
#define TBN 64
#define NEGV (-1e9f)
#define E_CONST 2.718281828459045f
#define MROWS (BB*TT)            // 2048

// ---------------- scratch layout (floats) ----------------
#define OF_H    0ull
#define OF_BIAS 6291456ull
#define OF_S    7340032ull
#define OF_QKV  OF_S
#define OF_BQKV (OF_S + 4718592ull)
#define OF_A    19922944ull
#define OF_X2   21495808ull
#define OF_F    23068672ull
#define OF_WQT  29360128ull
#define OF_WPT  31129600ull
#define OF_F1T  31719424ull
#define OF_F2T  34078720ull
#define SCRATCH_TOTAL 36438016ull

__device__ float g_scratch[SCRATCH_TOTAL];

// ---------------- helpers ----------------
__device__ __forceinline__ uint32_t smem_u32(const void* p) {
    uint32_t a;
    asm("{ .reg .u64 t; cvta.to.shared.u64 t, %1; cvt.u32.u64 %0, t; }" : "=r"(a) : "l"(p));
    return a;
}
__device__ __forceinline__ float f2tf32f(float f) {
    uint32_t r; asm("cvt.rna.tf32.f32 %0, %1;" : "=r"(r) : "f"(f));
    return __uint_as_float(r);
}
#define CP_ASYNC16(dst_u32, src_ptr) \
    asm volatile("cp.async.cg.shared.global [%0], [%1], 16;\n" :: "r"(dst_u32), "l"(__cvta_generic_to_global(src_ptr)))
#define CP_COMMIT() asm volatile("cp.async.commit_group;\n" ::: "memory")
#define CP_WAIT2()  asm volatile("cp.async.wait_group 2;\n" ::: "memory")
#define CP_WAIT1()  asm volatile("cp.async.wait_group 1;\n" ::: "memory")
#define CP_WAIT0()  asm volatile("cp.async.wait_group 0;\n" ::: "memory")

#define MMA_TF32(c0,c1,c2,c3,a0,a1,a2,a3,b0,b1) \
    asm volatile("mma.sync.aligned.m16n8k8.row.col.f32.tf32.tf32.f32 " \
                 "{%0,%1,%2,%3}, {%4,%5,%6,%7}, {%8,%9}, {%0,%1,%2,%3};\n" \
                 : "+f"(c0), "+f"(c1), "+f"(c2), "+f"(c3) \
                 : "r"(a0), "r"(a1), "r"(a2), "r"(a3), "r"(b0), "r"(b1))

#define LDSM_X4(d0,d1,d2,d3,addr) \
    asm volatile("ldmatrix.sync.aligned.m8n8.x4.shared.b16 {%0,%1,%2,%3}, [%4];\n" \
                 : "=r"(d0), "=r"(d1), "=r"(d2), "=r"(d3) : "r"(addr))

#define LDT 20
#define BM 128

// =======================================================================
// big-tile GEMM — 128x128, 3-stage, warp tile 32x64. For N>=2304 GEMMs.
// =======================================================================
#define BN2 128
#define GST2 3
#define GEMM_SMEM2 ((GST2*(BM+BN2)*LDT)*4)   // 61440

template <int EPI>  // 0 bias, 2 bias+gelu(+tf32)
__global__ __launch_bounds__(256, 2) void gemm_big(const float* __restrict__ A,
                                                   const float* __restrict__ Wt,
                                                   const float* __restrict__ bias,
                                                   float* __restrict__ C,
                                                   int N, int K) {
    extern __shared__ float dsm[];
    float* AsBase = dsm;
    float* BsBase = dsm + GST2 * BM * LDT;

    int tid = threadIdx.x;
    int warp = tid >> 5, lane = tid & 31;
    int wm = warp >> 1, wn = warp & 1;
    int g = lane >> 2, tig = lane & 3;
    int m0 = blockIdx.y * BM, n0 = blockIdx.x * BN2;

    int r0 = tid >> 2,            c0_ = (tid & 3) * 4;
    int r1 = (tid + 256) >> 2,    c1_ = ((tid + 256) & 3) * 4;

    uint32_t sA = smem_u32(AsBase);
    uint32_t sB = smem_u32(BsBase);
    const uint32_t bufA = BM * LDT * 4, bufB = BN2 * LDT * 4;

    int q = lane >> 3, l7 = lane & 7;
    int a_row = wm * 32 + (q & 1) * 8 + l7,  a_col = (q >> 1) * 4;
    int b_row = wn * 64 + (q >> 1) * 8 + l7, b_col = (q & 1) * 4;
    uint32_t aAddr0 = sA + (uint32_t)(a_row * LDT + a_col) * 4;
    uint32_t bAddr0 = sB + (uint32_t)(b_row * LDT + b_col) * 4;

    const int nk = K >> 4;

    #pragma unroll
    for (int pf = 0; pf < 2; pf++) {
        int k0 = pf * 16;
        CP_ASYNC16(sA + pf * bufA + (r0 * LDT + c0_) * 4, A + (size_t)(m0 + r0) * K + k0 + c0_);
        CP_ASYNC16(sA + pf * bufA + (r1 * LDT + c1_) * 4, A + (size_t)(m0 + r1) * K + k0 + c1_);
        CP_ASYNC16(sB + pf * bufB + (r0 * LDT + c0_) * 4, Wt + (size_t)(n0 + r0) * K + k0 + c0_);
        CP_ASYNC16(sB + pf * bufB + (r1 * LDT + c1_) * 4, Wt + (size_t)(n0 + r1) * K + k0 + c1_);
        CP_COMMIT();
    }

    float c[2][8][4];
    #pragma unroll
    for (int i = 0; i < 2; i++)
        #pragma unroll
        for (int j = 0; j < 8; j++)
            #pragma unroll
            for (int e = 0; e < 4; e++) c[i][j][e] = 0.f;

    for (int kt = 0; kt < nk; kt++) {
        int buf = kt % GST2;
        CP_WAIT1();
        __syncthreads();

        uint32_t aBuf = aAddr0 + buf * bufA;
        uint32_t bBuf = bAddr0 + buf * bufB;
        #pragma unroll
        for (int ks = 0; ks < 2; ks++) {
            uint32_t kOff = (uint32_t)(ks * 8) * 4;
            uint32_t a[2][4], b[8][2];
            #pragma unroll
            for (int i = 0; i < 2; i++)
                LDSM_X4(a[i][0], a[i][1], a[i][2], a[i][3],
                        aBuf + (uint32_t)(i * 16 * LDT) * 4 + kOff);
            #pragma unroll
            for (int p = 0; p < 4; p++)
                LDSM_X4(b[2*p][0], b[2*p][1], b[2*p+1][0], b[2*p+1][1],
                        bBuf + (uint32_t)(p * 16 * LDT) * 4 + kOff);
            #pragma unroll
            for (int i = 0; i < 2; i++)
                #pragma unroll
                for (int j = 0; j < 8; j++)
                    MMA_TF32(c[i][j][0], c[i][j][1], c[i][j][2], c[i][j][3],
                             a[i][0], a[i][1], a[i][2], a[i][3], b[j][0], b[j][1]);
        }

        if (kt + 2 < nk) {
            int k0 = (kt + 2) * 16;
            int nbuf = (kt + 2) % GST2;
            CP_ASYNC16(sA + nbuf * bufA + (r0 * LDT + c0_) * 4, A + (size_t)(m0 + r0) * K + k0 + c0_);
            CP_ASYNC16(sA + nbuf * bufA + (r1 * LDT + c1_) * 4, A + (size_t)(m0 + r1) * K + k0 + c1_);
            CP_ASYNC16(sB + nbuf * bufB + (r0 * LDT + c0_) * 4, Wt + (size_t)(n0 + r0) * K + k0 + c0_);
            CP_ASYNC16(sB + nbuf * bufB + (r1 * LDT + c1_) * 4, Wt + (size_t)(n0 + r1) * K + k0 + c1_);
        }
        CP_COMMIT();
    }

    #pragma unroll
    for (int i = 0; i < 2; i++) {
        int row0 = m0 + wm * 32 + i * 16 + g;
        #pragma unroll
        for (int j = 0; j < 8; j++) {
            int col = n0 + wn * 64 + j * 8 + 2 * tig;
            float b0 = bias[col], b1 = bias[col + 1];
            #pragma unroll
            for (int half = 0; half < 2; half++) {
                int r = row0 + half * 8;
                float v0 = c[i][j][half * 2 + 0] + b0;
                float v1 = c[i][j][half * 2 + 1] + b1;
                if (EPI == 2) {
                    v0 = 0.5f * v0 * (1.f + erff(v0 * 0.70710678118654752f));
                    v1 = 0.5f * v1 * (1.f + erff(v1 * 0.70710678118654752f));
                    v0 = f2tf32f(v0); v1 = f2tf32f(v1);
                }
                float2 o; o.x = v0; o.y = v1;
                *(float2*)(C + (size_t)r * N + col) = o;
            }
        }
    }
}

// =======================================================================
// n96 GEMM — 128x96 tile, 4-stage, warp tile 32x48, bias+residual.
// For N=768 GEMMs: grid 8x16 = 128 CTAs = one balanced wave on 148 SMs.
// Per-element accumulation order identical to other kernels.
// =======================================================================
#define BN3 96
#define GST3 4
#define GEMM_SMEM3 ((GST3*(BM+BN3)*LDT)*4)   // 71680

__global__ __launch_bounds__(256, 2) void gemm_n96(const float* __restrict__ A,
                                                   const float* __restrict__ Wt,
                                                   const float* __restrict__ bias,
                                                   const float* __restrict__ res,
                                                   float* __restrict__ C,
                                                   int N, int K) {
    extern __shared__ float dsm[];
    float* AsBase = dsm;
    float* BsBase = dsm + GST3 * BM * LDT;

    int tid = threadIdx.x;
    int warp = tid >> 5, lane = tid & 31;
    int wm = warp >> 1, wn = warp & 1;
    int g = lane >> 2, tig = lane & 3;
    int m0 = blockIdx.y * BM, n0 = blockIdx.x * BN3;

    // A: 128 rows x 16 cols per stage = 512 chunks; 2 per thread
    int ar0 = tid >> 2,            ac0 = (tid & 3) * 4;
    int ar1 = (tid + 256) >> 2,    ac1 = ((tid + 256) & 3) * 4;
    // B: 96 rows x 16 cols = 384 chunks; 1 per thread + 1 for tid<128
    int br0 = tid >> 2,            bc0 = (tid & 3) * 4;
    int br1 = (tid + 256) >> 2,    bc1 = ((tid + 256) & 3) * 4;
    bool hasB1 = (tid < 128);

    uint32_t sA = smem_u32(AsBase);
    uint32_t sB = smem_u32(BsBase);
    const uint32_t bufA = BM * LDT * 4, bufB = BN3 * LDT * 4;

    int q = lane >> 3, l7 = lane & 7;
    int a_row = wm * 32 + (q & 1) * 8 + l7,  a_col = (q >> 1) * 4;
    int b_row = wn * 48 + (q >> 1) * 8 + l7, b_col = (q & 1) * 4;
    uint32_t aAddr0 = sA + (uint32_t)(a_row * LDT + a_col) * 4;
    uint32_t bAddr0 = sB + (uint32_t)(b_row * LDT + b_col) * 4;

    const int nk = K >> 4;

    #pragma unroll
    for (int pf = 0; pf < 3; pf++) {
        int k0 = pf * 16;
        CP_ASYNC16(sA + pf * bufA + (ar0 * LDT + ac0) * 4, A + (size_t)(m0 + ar0) * K + k0 + ac0);
        CP_ASYNC16(sA + pf * bufA + (ar1 * LDT + ac1) * 4, A + (size_t)(m0 + ar1) * K + k0 + ac1);
        CP_ASYNC16(sB + pf * bufB + (br0 * LDT + bc0) * 4, Wt + (size_t)(n0 + br0) * K + k0 + bc0);
        if (hasB1)
            CP_ASYNC16(sB + pf * bufB + (br1 * LDT + bc1) * 4, Wt + (size_t)(n0 + br1) * K + k0 + bc1);
        CP_COMMIT();
    }

    float c[2][6][4];
    #pragma unroll
    for (int i = 0; i < 2; i++)
        #pragma unroll
        for (int j = 0; j < 6; j++)
            #pragma unroll
            for (int e = 0; e < 4; e++) c[i][j][e] = 0.f;

    for (int kt = 0; kt < nk; kt++) {
        int buf = kt & (GST3 - 1);
        CP_WAIT2();
        __syncthreads();

        uint32_t aBuf = aAddr0 + buf * bufA;
        uint32_t bBuf = bAddr0 + buf * bufB;
        #pragma unroll
        for (int ks = 0; ks < 2; ks++) {
            uint32_t kOff = (uint32_t)(ks * 8) * 4;
            uint32_t a[2][4], b[6][2];
            #pragma unroll
            for (int i = 0; i < 2; i++)
                LDSM_X4(a[i][0], a[i][1], a[i][2], a[i][3],
                        aBuf + (uint32_t)(i * 16 * LDT) * 4 + kOff);
            #pragma unroll
            for (int p = 0; p < 3; p++)
                LDSM_X4(b[2*p][0], b[2*p][1], b[2*p+1][0], b[2*p+1][1],
                        bBuf + (uint32_t)(p * 16 * LDT) * 4 + kOff);
            #pragma unroll
            for (int i = 0; i < 2; i++)
                #pragma unroll
                for (int j = 0; j < 6; j++)
                    MMA_TF32(c[i][j][0], c[i][j][1], c[i][j][2], c[i][j][3],
                             a[i][0], a[i][1], a[i][2], a[i][3], b[j][0], b[j][1]);
        }

        if (kt + 3 < nk) {
            int k0 = (kt + 3) * 16;
            int nbuf = (kt + 3) & (GST3 - 1);
            CP_ASYNC16(sA + nbuf * bufA + (ar0 * LDT + ac0) * 4, A + (size_t)(m0 + ar0) * K + k0 + ac0);
            CP_ASYNC16(sA + nbuf * bufA + (ar1 * LDT + ac1) * 4, A + (size_t)(m0 + ar1) * K + k0 + ac1);
            CP_ASYNC16(sB + nbuf * bufB + (br0 * LDT + bc0) * 4, Wt + (size_t)(n0 + br0) * K + k0 + bc0);
            if (hasB1)
                CP_ASYNC16(sB + nbuf * bufB + (br1 * LDT + bc1) * 4, Wt + (size_t)(n0 + br1) * K + k0 + bc1);
        }
        CP_COMMIT();
    }

    #pragma unroll
    for (int i = 0; i < 2; i++) {
        int row0 = m0 + wm * 32 + i * 16 + g;
        #pragma unroll
        for (int j = 0; j < 6; j++) {
            int col = n0 + wn * 48 + j * 8 + 2 * tig;
            float b0 = bias[col], b1 = bias[col + 1];
            #pragma unroll
            for (int half = 0; half < 2; half++) {
                int r = row0 + half * 8;
                float2 r2 = *(const float2*)(res + (size_t)r * N + col);
                float2 o;
                o.x = c[i][j][half * 2 + 0] + b0 + r2.x;
                o.y = c[i][j][half * 2 + 1] + b1 + r2.y;
                *(float2*)(C + (size_t)r * N + col) = o;
            }
        }
    }
}

// ---------------- merged transposes (tf32-rounded) ----------------
__global__ __launch_bounds__(256) void transpose_attn(const float* __restrict__ wq,
                                                      const float* __restrict__ wk,
                                                      const float* __restrict__ wv,
                                                      const float* __restrict__ wp,
                                                      float* __restrict__ dst) {
    __shared__ float t[32][33];
    int z = blockIdx.z;
    const float* W = (z == 0) ? wq : (z == 1) ? wk : (z == 2) ? wv : wp;
    float* Wt = dst + (size_t)z * 589824;
    int n0 = blockIdx.x * 32, k0 = blockIdx.y * 32;
    int tx = threadIdx.x, ty = threadIdx.y;
    #pragma unroll
    for (int i = 0; i < 32; i += 8)
        t[ty + i][tx] = W[(size_t)(k0 + ty + i) * DD + n0 + tx];
    __syncthreads();
    #pragma unroll
    for (int i = 0; i < 32; i += 8)
        Wt[(size_t)(n0 + ty + i) * DD + k0 + tx] = f2tf32f(t[tx][ty + i]);
}

__global__ __launch_bounds__(256) void transpose_ffn(const float* __restrict__ f1w,
                                                     float* __restrict__ f1T,
                                                     const float* __restrict__ f2w,
                                                     float* __restrict__ f2T) {
    __shared__ float t[32][33];
    int z = blockIdx.z;
    const float* W; float* Wt; int K, N, n0, k0;
    if (z == 0) { W = f1w; Wt = f1T; K = DD;  N = FFC; n0 = blockIdx.x * 32; k0 = blockIdx.y * 32; }
    else        { W = f2w; Wt = f2T; K = FFC; N = DD;  n0 = blockIdx.y * 32; k0 = blockIdx.x * 32; }
    int tx = threadIdx.x, ty = threadIdx.y;
    #pragma unroll
    for (int i = 0; i < 32; i += 8)
        t[ty + i][tx] = W[(size_t)(k0 + ty + i) * N + n0 + tx];
    __syncthreads();
    #pragma unroll
    for (int i = 0; i < 32; i += 8)
        Wt[(size_t)(n0 + ty + i) * K + k0 + tx] = f2tf32f(t[tx][ty + i]);
}

__global__ void concat_bias(const float* __restrict__ a, const float* __restrict__ b,
                            const float* __restrict__ c, float* __restrict__ o) {
    int t = blockIdx.x * 256 + threadIdx.x;
    if (t < 768) o[t] = a[t];
    else if (t < 1536) o[t] = b[t - 768];
    else if (t < 2304) o[t] = c[t - 1536];
}

// ---------------- LayerNorm (tf32-rounded output) ----------------
__global__ __launch_bounds__(256) void ln_kernel(const float* __restrict__ x,
                                                 const float* __restrict__ g,
                                                 const float* __restrict__ b,
                                                 float* __restrict__ out) {
    int row = blockIdx.x;
    const float* xr = x + (size_t)row * DD;
    float s = 0.f, s2 = 0.f;
    for (int i = threadIdx.x; i < DD; i += 256) { float v = xr[i]; s += v; s2 += v * v; }
    #pragma unroll
    for (int o = 16; o > 0; o >>= 1) {
        s  += __shfl_xor_sync(0xffffffffu, s,  o);
        s2 += __shfl_xor_sync(0xffffffffu, s2, o);
    }
    __shared__ float ws[8], ws2[8];
    int w = threadIdx.x >> 5, l = threadIdx.x & 31;
    if (l == 0) { ws[w] = s; ws2[w] = s2; }
    __syncthreads();
    if (w == 0) {
        s  = (l < 8) ? ws[l]  : 0.f;
        s2 = (l < 8) ? ws2[l] : 0.f;
        #pragma unroll
        for (int o = 4; o > 0; o >>= 1) {
            s  += __shfl_xor_sync(0xffffffffu, s,  o);
            s2 += __shfl_xor_sync(0xffffffffu, s2, o);
        }
        if (l == 0) { ws[0] = s; ws2[0] = s2; }
    }
    __syncthreads();
    float mean = ws[0] * (1.f / DD);
    float var  = ws2[0] * (1.f / DD) - mean * mean;
    float inv  = rsqrtf(var + 1e-5f);
    float* orow = out + (size_t)row * DD;
    for (int i = threadIdx.x; i < DD; i += 256)
        orow[i] = f2tf32f((xr[i] - mean) * inv * g[i] + b[i]);
}

// ---------------- temporal bias w/ masks baked in (fast math) ----------------
__global__ __launch_bounds__(256) void bias_kernel(const float* __restrict__ tm,
                                                   const int* __restrict__ pm,
                                                   const float* __restrict__ t1w,
                                                   const float* __restrict__ t1b,
                                                   const float* __restrict__ t2w,
                                                   const float* __restrict__ t2b) {
    __shared__ float w1[TBN], b1[TBN], w2[TBN];
    int t = threadIdx.x;
    if (t < TBN) { w1[t] = t1w[t]; b1[t] = t1b[t]; w2[t] = t2w[t]; }
    __syncthreads();
    size_t idx = (size_t)blockIdx.x * 256 + t;
    int rem = (int)(idx % (TT * TT));
    int i = rem / TT, j = rem % TT;
    float u = __fdividef(1.f, __logf(E_CONST + tm[idx]));
    float s = t2b[0];
    #pragma unroll
    for (int k = 0; k < TBN; k++) {
        float z = fmaf(u, w1[k], b1[k]);
        z = (z > 0.f) ? z : 0.2f * z;
        s = fmaf(z, w2[k], s);
    }
    bool masked = (pm[idx] == 0) || (j > i && i > 0);
    g_scratch[OF_BIAS + idx] = masked ? NEGV : s;
}

// =======================================================================
// flash attention (validated R5) — unchanged
// =======================================================================
#define SQ_LD 68
#define SV_LD 72
#define FS_Q    0
#define FS_K    (64*68)
#define FS_V    (FS_K + 2*64*68)
#define FS_P    (FS_V + 2*64*72)
#define FS_STAT (FS_P + 64*68)
#define FS_TOT  ((FS_STAT + 256) * 4)

__global__ __launch_bounds__(256, 2) void flash_kernel(const float* __restrict__ qkv,
                                                       float* __restrict__ outA) {
    extern __shared__ float fs[];
    float* sQ = fs + FS_Q;
    float* sK = fs + FS_K;
    float* sV = fs + FS_V;
    float* sP = fs + FS_P;
    float* sMax = fs + FS_STAT;
    float* sSum = fs + FS_STAT + 128;
    uint32_t sKu = smem_u32(sK), sVu = smem_u32(sV);

    int tid = threadIdx.x;
    int warp = tid >> 5, lane = tid & 31;
    int wm = warp >> 1, wn = warp & 1;
    int g = lane >> 2, tig = lane & 3;
    int i0 = blockIdx.x * 64;
    int bh = blockIdx.y, b = bh / HH, h = bh % HH;

    const float* base = qkv + (size_t)b * TT * 2304 + h * 64;
    const float* biasB = g_scratch + OF_BIAS + (size_t)b * TT * TT;

    for (int ch = tid; ch < 1024; ch += 256) {
        int r = ch >> 4, cc = (ch & 15) * 4;
        float4 v = *(const float4*)(base + (size_t)(i0 + r) * 2304 + cc);
        float4 o;
        o.x = f2tf32f(v.x * 0.125f); o.y = f2tf32f(v.y * 0.125f);
        o.z = f2tf32f(v.z * 0.125f); o.w = f2tf32f(v.w * 0.125f);
        *(float4*)(sQ + r * SQ_LD + cc) = o;
    }

    float o[4][4];
    #pragma unroll
    for (int j = 0; j < 4; j++)
        #pragma unroll
        for (int e = 0; e < 4; e++) o[j][e] = 0.f;
    float m0r = -INFINITY, m1r = -INFINITY, l0 = 0.f, l1 = 0.f;

    int ntiles = (i0 == 0) ? (TT / 64) : (i0 >> 6) + 1;
    int rw0 = wm * 16 + g, rw1 = rw0 + 8;

    {
        const float* kb_ = base + 768;
        const float* vb_ = base + 1536;
        for (int ch = tid; ch < 1024; ch += 256) {
            int r = ch >> 4, cc = (ch & 15) * 4;
            CP_ASYNC16(sKu + (r * SQ_LD + cc) * 4, kb_ + (size_t)r * 2304 + cc);
            CP_ASYNC16(sVu + (r * SV_LD + cc) * 4, vb_ + (size_t)r * 2304 + cc);
        }
        CP_COMMIT();
    }

    for (int t = 0; t < ntiles; t++) {
        int j0 = t * 64, buf = t & 1;
        CP_WAIT0();
        __syncthreads();

        float c[4][4];
        #pragma unroll
        for (int j = 0; j < 4; j++)
            #pragma unroll
            for (int e = 0; e < 4; e++) c[j][e] = 0.f;
        const float* kS = sK + buf * 64 * SQ_LD;
        #pragma unroll
        for (int kb = 0; kb < 64; kb += 8) {
            uint32_t a[4], bfr[4][2];
            int qr = wm * 16;
            a[0] = __float_as_uint(sQ[(qr + g)     * SQ_LD + kb + tig]);
            a[1] = __float_as_uint(sQ[(qr + 8 + g) * SQ_LD + kb + tig]);
            a[2] = __float_as_uint(sQ[(qr + g)     * SQ_LD + kb + tig + 4]);
            a[3] = __float_as_uint(sQ[(qr + 8 + g) * SQ_LD + kb + tig + 4]);
            #pragma unroll
            for (int j = 0; j < 4; j++) {
                int r = wn * 32 + j * 8 + g;
                bfr[j][0] = __float_as_uint(kS[r * SQ_LD + kb + tig]);
                bfr[j][1] = __float_as_uint(kS[r * SQ_LD + kb + tig + 4]);
            }
            #pragma unroll
            for (int j = 0; j < 4; j++)
                MMA_TF32(c[j][0], c[j][1], c[j][2], c[j][3],
                         a[0], a[1], a[2], a[3], bfr[j][0], bfr[j][1]);
        }

        int gi0 = i0 + rw0, gi1 = i0 + rw1;
        #pragma unroll
        for (int j = 0; j < 4; j++) {
            int gj = j0 + wn * 32 + j * 8 + 2 * tig;
            float2 b0 = *(const float2*)(biasB + (size_t)gi0 * TT + gj);
            float2 b1 = *(const float2*)(biasB + (size_t)gi1 * TT + gj);
            c[j][0] += b0.x; c[j][1] += b0.y;
            c[j][2] += b1.x; c[j][3] += b1.y;
        }

        float mx0 = c[0][0], mx1 = c[0][2];
        #pragma unroll
        for (int j = 0; j < 4; j++) {
            mx0 = fmaxf(mx0, fmaxf(c[j][0], c[j][1]));
            mx1 = fmaxf(mx1, fmaxf(c[j][2], c[j][3]));
        }
        mx0 = fmaxf(mx0, __shfl_xor_sync(0xffffffffu, mx0, 1));
        mx0 = fmaxf(mx0, __shfl_xor_sync(0xffffffffu, mx0, 2));
        mx1 = fmaxf(mx1, __shfl_xor_sync(0xffffffffu, mx1, 1));
        mx1 = fmaxf(mx1, __shfl_xor_sync(0xffffffffu, mx1, 2));
        if (tig == 0) { sMax[wn * 64 + rw0] = mx0; sMax[wn * 64 + rw1] = mx1; }
        __syncthreads();
        float mxc0 = fmaxf(sMax[rw0], sMax[64 + rw0]);
        float mxc1 = fmaxf(sMax[rw1], sMax[64 + rw1]);

        float mn0 = fmaxf(m0r, mxc0), mn1 = fmaxf(m1r, mxc1);
        float al0 = __expf(m0r - mn0), al1 = __expf(m1r - mn1);

        float sum0 = 0.f, sum1 = 0.f;
        #pragma unroll
        for (int j = 0; j < 4; j++) {
            int cw = wn * 32 + j * 8 + 2 * tig;
            float p00 = __expf(c[j][0] - mn0), p01 = __expf(c[j][1] - mn0);
            float p10 = __expf(c[j][2] - mn1), p11 = __expf(c[j][3] - mn1);
            sum0 += p00 + p01; sum1 += p10 + p11;
            float2 q0; q0.x = p00; q0.y = p01;
            float2 q1; q1.x = p10; q1.y = p11;
            *(float2*)(sP + rw0 * SQ_LD + cw) = q0;
            *(float2*)(sP + rw1 * SQ_LD + cw) = q1;
        }
        sum0 += __shfl_xor_sync(0xffffffffu, sum0, 1);
        sum0 += __shfl_xor_sync(0xffffffffu, sum0, 2);
        sum1 += __shfl_xor_sync(0xffffffffu, sum1, 1);
        sum1 += __shfl_xor_sync(0xffffffffu, sum1, 2);
        if (tig == 0) { sSum[wn * 64 + rw0] = sum0; sSum[wn * 64 + rw1] = sum1; }
        __syncthreads();
        float sc0 = sSum[rw0] + sSum[64 + rw0];
        float sc1 = sSum[rw1] + sSum[64 + rw1];

        l0 = l0 * al0 + sc0;  l1 = l1 * al1 + sc1;
        m0r = mn0;  m1r = mn1;
        #pragma unroll
        for (int j = 0; j < 4; j++) {
            o[j][0] *= al0; o[j][1] *= al0;
            o[j][2] *= al1; o[j][3] *= al1;
        }

        if (t + 1 < ntiles) {
            int nj0 = (t + 1) * 64, nb = buf ^ 1;
            const float* kb_ = base + 768;
            const float* vb_ = base + 1536;
            for (int ch = tid; ch < 1024; ch += 256) {
                int r = ch >> 4, cc = (ch & 15) * 4;
                CP_ASYNC16(sKu + (nb * 64 * SQ_LD + r * SQ_LD + cc) * 4, kb_ + (size_t)(nj0 + r) * 2304 + cc);
                CP_ASYNC16(sVu + (nb * 64 * SV_LD + r * SV_LD + cc) * 4, vb_ + (size_t)(nj0 + r) * 2304 + cc);
            }
            CP_COMMIT();
        }

        const float* vS = sV + buf * 64 * SV_LD;
        #pragma unroll
        for (int kb = 0; kb < 64; kb += 8) {
            uint32_t a[4], bfr[4][2];
            int pr = wm * 16;
            a[0] = __float_as_uint(sP[(pr + g)     * SQ_LD + kb + tig]);
            a[1] = __float_as_uint(sP[(pr + 8 + g) * SQ_LD + kb + tig]);
            a[2] = __float_as_uint(sP[(pr + g)     * SQ_LD + kb + tig + 4]);
            a[3] = __float_as_uint(sP[(pr + 8 + g) * SQ_LD + kb + tig + 4]);
            #pragma unroll
            for (int j = 0; j < 4; j++) {
                int nc = wn * 32 + j * 8 + g;
                bfr[j][0] = __float_as_uint(vS[(kb + tig)     * SV_LD + nc]);
                bfr[j][1] = __float_as_uint(vS[(kb + tig + 4) * SV_LD + nc]);
            }
            #pragma unroll
            for (int j = 0; j < 4; j++)
                MMA_TF32(o[j][0], o[j][1], o[j][2], o[j][3],
                         a[0], a[1], a[2], a[3], bfr[j][0], bfr[j][1]);
        }
        __syncthreads();
    }

    float inv0 = 1.f / l0, inv1 = 1.f / l1;
    int gr0 = b * TT + i0 + wm * 16 + g, gr1 = gr0 + 8;
    #pragma unroll
    for (int j = 0; j < 4; j++) {
        int col = h * 64 + wn * 32 + j * 8 + 2 * tig;
        float2 o0, o1;
        o0.x = f2tf32f(o[j][0] * inv0); o0.y = f2tf32f(o[j][1] * inv0);
        o1.x = f2tf32f(o[j][2] * inv1); o1.y = f2tf32f(o[j][3] * inv1);
        *(float2*)(outA + (size_t)gr0 * DD + col) = o0;
        *(float2*)(outA + (size_t)gr1 * DD + col) = o1;
    }
}

// ---------------- launch ----------------
extern "C" void kernel_launch(void* const* d_in, const int* in_sizes, int n_in,
                              void* d_out, int out_size) {
    const float* x     = (const float*)d_in[0];
    const float* tmat  = (const float*)d_in[1];
    const int*   pm    = (const int*)d_in[2];
    const float* wq = (const float*)d_in[3],  *bq = (const float*)d_in[4];
    const float* wk = (const float*)d_in[5],  *bk = (const float*)d_in[6];
    const float* wv = (const float*)d_in[7],  *bv = (const float*)d_in[8];
    const float* wp = (const float*)d_in[9],  *bp = (const float*)d_in[10];
    const float* t1w = (const float*)d_in[11], *t1b = (const float*)d_in[12];
    const float* t2w = (const float*)d_in[13], *t2b = (const float*)d_in[14];
    const float* f1w = (const float*)d_in[15], *f1b = (const float*)d_in[16];
    const float* f2w = (const float*)d_in[17], *f2b = (const float*)d_in[18];
    const float* ln1g = (const float*)d_in[19], *ln1b = (const float*)d_in[20];
    const float* ln2g = (const float*)d_in[21], *ln2b = (const float*)d_in[22];
    float* out = (float*)d_out;

    float* sc = nullptr;
    cudaGetSymbolAddress((void**)&sc, g_scratch);
    float* gH    = sc + OF_H;
    float* gQKV  = sc + OF_QKV;
    float* gBQKV = sc + OF_BQKV;
    float* gA    = sc + OF_A;
    float* gX2   = sc + OF_X2;
    float* gF    = sc + OF_F;
    float* wcT   = sc + OF_WQT;
    float* wpT   = sc + OF_WPT;
    float* f1T   = sc + OF_F1T;
    float* f2T   = sc + OF_F2T;

    // lazy one-time stream/event setup (runs on the uncaptured correctness call)
    static cudaStream_t sBias = nullptr, sTr = nullptr;
    static cudaEvent_t eFork = nullptr, eBias = nullptr, eTr = nullptr;
    if (sBias == nullptr) {
        cudaStreamCreateWithFlags(&sBias, cudaStreamNonBlocking);
        cudaStreamCreateWithFlags(&sTr, cudaStreamNonBlocking);
        cudaEventCreateWithFlags(&eFork, cudaEventDisableTiming);
        cudaEventCreateWithFlags(&eBias, cudaEventDisableTiming);
        cudaEventCreateWithFlags(&eTr, cudaEventDisableTiming);
        cudaFuncSetAttribute(gemm_big<0>, cudaFuncAttributeMaxDynamicSharedMemorySize, GEMM_SMEM2);
        cudaFuncSetAttribute(gemm_big<2>, cudaFuncAttributeMaxDynamicSharedMemorySize, GEMM_SMEM2);
        cudaFuncSetAttribute(gemm_n96, cudaFuncAttributeMaxDynamicSharedMemorySize, GEMM_SMEM3);
        cudaFuncSetAttribute(flash_kernel, cudaFuncAttributeMaxDynamicSharedMemorySize, FS_TOT);
    }

    dim3 tb(32, 8);

    // fork
    cudaEventRecord(eFork, 0);
    cudaStreamWaitEvent(sBias, eFork, 0);
    cudaStreamWaitEvent(sTr, eFork, 0);

    // branch B: temporal bias (needed only by flash)
    bias_kernel<<<(BB * TT * TT) / 256, 256, 0, sBias>>>(tmat, pm, t1w, t1b, t2w, t2b);
    cudaEventRecord(eBias, sBias);

    // branch C: weight transposes + bias concat (needed by GEMMs)
    transpose_attn<<<dim3(24, 24, 4), tb, 0, sTr>>>(wq, wk, wv, wp, wcT);
    transpose_ffn<<<dim3(96, 24, 2), tb, 0, sTr>>>(f1w, f1T, f2w, f2T);
    concat_bias<<<9, 256, 0, sTr>>>(bq, bk, bv, gBQKV);
    cudaEventRecord(eTr, sTr);

    // main chain
    ln_kernel<<<MROWS, 256>>>(x, ln1g, ln1b, gH);
    cudaStreamWaitEvent(0, eTr, 0);
    gemm_big<0><<<dim3(2304 / BN2, MROWS / BM), 256, GEMM_SMEM2>>>(gH, wcT, gBQKV, gQKV, 2304, DD);

    cudaStreamWaitEvent(0, eBias, 0);
    flash_kernel<<<dim3(TT / 64, BB * HH), 256, FS_TOT>>>(gQKV, gA);

    gemm_n96<<<dim3(DD / BN3, MROWS / BM), 256, GEMM_SMEM3>>>(gA, wpT, bp, x, gX2, DD, DD);

    ln_kernel<<<MROWS, 256>>>(gX2, ln2g, ln2b, gH);
    gemm_big<2><<<dim3(FFC / BN2, MROWS / BM), 256, GEMM_SMEM2>>>(gH, f1T, f1b, gF, FFC, DD);
    gemm_n96<<<dim3(DD / BN3, MROWS / BM), 256, GEMM_SMEM3>>>(gF, f2T, f2b, gX2, out, DD, FFC);
}